// round 2
// baseline (speedup 1.0000x reference)
#include <cuda_runtime.h>
#include <math.h>
#include <stdint.h>

// Problem dims (fixed by the dataset)
namespace {
constexpr int Bc  = 2;
constexpr int Sc  = 2048;
constexpr int Hc  = 4096;
constexpr int NHc = 32;
constexpr int HDc = 128;
constexpr int Ic  = 11008;
constexpr int Tc  = Bc * Sc;        // 4096
constexpr int HALFc = HDc / 2;      // 64
constexpr float EPSc = 1e-6f;
constexpr float SCALEc = 0.08838834764831843f; // HD^-0.5
}

// ------------------------------------------------------------------
// Device scratch (static allocation — no cudaMalloc allowed)
// ------------------------------------------------------------------
__device__ float g_res1  [(size_t)Tc * Hc];          //  64 MB
__device__ float g_normed[(size_t)Tc * Hc];          //  64 MB (reused for normed2)
__device__ float g_qkv   [(size_t)Tc * 3 * Hc];      // 192 MB
__device__ float g_attn  [(size_t)Tc * Hc];          //  64 MB
__device__ float g_scores[(size_t)Bc * NHc * Sc * Sc]; // 1 GB (scores, then probs in-place)
__device__ float g_gu    [(size_t)Tc * 2 * Ic];      // 360 MB
__device__ float g_act   [(size_t)Tc * Ic];          // 180 MB

// ------------------------------------------------------------------
// Block reductions (256 threads)
// ------------------------------------------------------------------
__device__ __forceinline__ float block_reduce_sum_256(float v) {
    #pragma unroll
    for (int o = 16; o > 0; o >>= 1) v += __shfl_down_sync(0xffffffffu, v, o);
    __shared__ float red[8];
    int w = threadIdx.x >> 5, l = threadIdx.x & 31;
    if (l == 0) red[w] = v;
    __syncthreads();
    if (w == 0) {
        float x = (l < 8) ? red[l] : 0.f;
        #pragma unroll
        for (int o = 4; o > 0; o >>= 1) x += __shfl_down_sync(0xffu, x, o);
        if (l == 0) red[0] = x;
    }
    __syncthreads();
    float r = red[0];
    __syncthreads();
    return r;
}

__device__ __forceinline__ float block_reduce_max_256(float v) {
    #pragma unroll
    for (int o = 16; o > 0; o >>= 1) v = fmaxf(v, __shfl_down_sync(0xffffffffu, v, o));
    __shared__ float red[8];
    int w = threadIdx.x >> 5, l = threadIdx.x & 31;
    if (l == 0) red[w] = v;
    __syncthreads();
    if (w == 0) {
        float x = (l < 8) ? red[l] : -INFINITY;
        #pragma unroll
        for (int o = 4; o > 0; o >>= 1) x = fmaxf(x, __shfl_down_sync(0xffu, x, o));
        if (l == 0) red[0] = x;
    }
    __syncthreads();
    float r = red[0];
    __syncthreads();
    return r;
}

// ------------------------------------------------------------------
// Fused (optional add) + RMSNorm. One block (256 thr) per row of H=4096.
// If b != nullptr: s = a + b, write s to sum_out. Norm(s)*w -> out.
// ------------------------------------------------------------------
__global__ __launch_bounds__(256) void add_rmsnorm_kernel(
    const float* __restrict__ a, const float* __restrict__ b,
    const float* __restrict__ w, float* __restrict__ sum_out,
    float* __restrict__ out)
{
    int row = blockIdx.x;
    const float4* a4 = (const float4*)(a + (size_t)row * Hc);
    const float4* b4 = b ? (const float4*)(b + (size_t)row * Hc) : nullptr;
    const float4* w4 = (const float4*)w;
    float4* o4 = (float4*)(out + (size_t)row * Hc);
    float4* s4 = sum_out ? (float4*)(sum_out + (size_t)row * Hc) : nullptr;

    float4 v[4];
    float ss = 0.f;
    #pragma unroll
    for (int it = 0; it < 4; it++) {
        int idx = threadIdx.x + it * 256;
        float4 va = a4[idx];
        if (b4) {
            float4 vb = b4[idx];
            va.x += vb.x; va.y += vb.y; va.z += vb.z; va.w += vb.w;
        }
        v[it] = va;
        ss += va.x * va.x + va.y * va.y + va.z * va.z + va.w * va.w;
    }
    float tot = block_reduce_sum_256(ss);
    float scale = rsqrtf(tot / (float)Hc + EPSc);
    #pragma unroll
    for (int it = 0; it < 4; it++) {
        int idx = threadIdx.x + it * 256;
        if (s4) s4[idx] = v[it];
        float4 vw = w4[idx];
        o4[idx] = make_float4(v[it].x * scale * vw.x, v[it].y * scale * vw.y,
                              v[it].z * scale * vw.z, v[it].w * scale * vw.w);
    }
}

// ------------------------------------------------------------------
// RoPE in-place on q and k halves of g_qkv.
// idx -> (t, m(q/k), h, d) ; pair (d, d+64)
// ------------------------------------------------------------------
__global__ __launch_bounds__(256) void rope_kernel(
    float* __restrict__ qkv, const float* __restrict__ cosp,
    const float* __restrict__ sinp)
{
    int idx = blockIdx.x * 256 + threadIdx.x;   // Tc*2*NHc*HALFc = 16,777,216
    int d = idx & (HALFc - 1);
    int h = (idx >> 6) & (NHc - 1);
    int m = (idx >> 11) & 1;
    int t = idx >> 12;
    float* p = qkv + (size_t)t * (3 * Hc) + m * Hc + h * HDc + d;
    float x1 = p[0];
    float x2 = p[HALFc];
    float c = cosp[(size_t)t * HALFc + d];
    float s = sinp[(size_t)t * HALFc + d];
    p[0]     = x1 * c - x2 * s;
    p[HALFc] = x1 * s + x2 * c;
}

// ------------------------------------------------------------------
// Causal softmax in-place on g_scores.
// block = (i row, z = b*NH+h). Reads j<=i, writes probs for j<=i and
// zeros for i < j < rowblock_end (128-aligned) so P@V's K-limit is safe.
// ------------------------------------------------------------------
__global__ __launch_bounds__(256) void softmax_kernel(float* __restrict__ scores)
{
    int i = blockIdx.x;
    int z = blockIdx.y;
    float* row = scores + (size_t)z * Sc * Sc + (size_t)i * Sc;
    int nvalid = i + 1;

    float vals[8];
    float mx = -INFINITY;
    #pragma unroll
    for (int it = 0; it < 8; it++) {
        int j = threadIdx.x + it * 256;
        float v = (j < nvalid) ? row[j] : -INFINITY;
        vals[it] = v;
        mx = fmaxf(mx, v);
    }
    float M = block_reduce_max_256(mx);
    float sum = 0.f;
    #pragma unroll
    for (int it = 0; it < 8; it++) {
        int j = threadIdx.x + it * 256;
        float e = (j < nvalid) ? __expf(vals[it] - M) : 0.f;
        vals[it] = e;
        sum += e;
    }
    float tot = block_reduce_sum_256(sum);
    float inv = 1.f / tot;
    int zero_end = ((i >> 7) + 1) << 7;   // end of this 128-row block
    #pragma unroll
    for (int it = 0; it < 8; it++) {
        int j = threadIdx.x + it * 256;
        if (j < zero_end) row[j] = vals[it] * inv;  // vals==0 for j>i
    }
}

// ------------------------------------------------------------------
// SiLU(gate) * up
// ------------------------------------------------------------------
__global__ __launch_bounds__(256) void silu_mul_kernel(
    const float* __restrict__ gu, float* __restrict__ act)
{
    int t = blockIdx.y;
    int i = blockIdx.x * 256 + threadIdx.x;      // Ic = 43*256
    float g = gu[(size_t)t * (2 * Ic) + i];
    float u = gu[(size_t)t * (2 * Ic) + Ic + i];
    float s = g / (1.f + __expf(-g));
    act[(size_t)t * Ic + i] = s * u;
}

// ------------------------------------------------------------------
// Generic batched SGEMM: C = alpha * A @ op(B) [+ ADD]
// 128x128x16 tiles, 8x8 micro-tiles (split 4+4 for conflict-free LDS),
// 256 threads. Batch via blockIdx.z with (batch, head) strides, heads=NHc.
// TRANSB : B is N x K row-major (C[i,j] = sum_k A[i,k] * B[j,k])
// CAUSAL_SKIP : skip (don't compute/write) blocks fully above diagonal
// KLIMIT : K loop ends at rowBase + 128 (P@V causal truncation)
// ------------------------------------------------------------------
template<bool TRANSB, bool ADDC, bool CAUSAL_SKIP, bool KLIMIT>
__global__ __launch_bounds__(256) void sgemm_kernel(
    const float* __restrict__ A0, const float* __restrict__ B0,
    float* __restrict__ C0, const float* __restrict__ ADD0,
    int M, int N, int K, int lda, int ldb, int ldc,
    long long sAb, long long sAh, long long sBb, long long sBh,
    long long sCb, long long sCh, float alpha)
{
    constexpr int BM = 128, BN = 128, BK = 16;

    int z  = blockIdx.z;
    int zb = z / NHc, zh = z % NHc;
    const float* A = A0 + zb * sAb + zh * sAh;
    const float* B = B0 + zb * sBb + zh * sBh;
    float*       C = C0 + zb * sCb + zh * sCh;

    int rowBase = blockIdx.y * BM;
    int colBase = blockIdx.x * BN;
    if (CAUSAL_SKIP && colBase > rowBase + BM - 1) return;

    int kEnd = KLIMIT ? min(K, rowBase + BM) : K;

    __shared__ float As[BK][BM];
    __shared__ float Bs[BK][BN];

    int tid = threadIdx.x;
    int tx = tid & 15;        // 0..15
    int ty = tid >> 4;        // 0..15

    float acc[8][8];
    #pragma unroll
    for (int i = 0; i < 8; i++)
        #pragma unroll
        for (int j = 0; j < 8; j++) acc[i][j] = 0.f;

    // A-tile (and B-tile when TRANSB) load indices: 128 rows x 16 k
    int arow = tid >> 2;            // 0..63 (+64 on second pass)
    int ac4  = (tid & 3) * 4;       // k offset within tile
    // B-tile NN load indices: 16 k x 128 n
    int bk = tid >> 5;              // 0..7 (+8 on second pass)
    int bc = (tid & 31) * 4;        // n offset within tile

    for (int k0 = 0; k0 < kEnd; k0 += BK) {
        // Load A tile (transposed into As[k][m])
        #pragma unroll
        for (int l = 0; l < 2; l++) {
            int r = arow + l * 64;
            float4 va = *(const float4*)(A + (size_t)(rowBase + r) * lda + k0 + ac4);
            As[ac4 + 0][r] = va.x;
            As[ac4 + 1][r] = va.y;
            As[ac4 + 2][r] = va.z;
            As[ac4 + 3][r] = va.w;
        }
        // Load B tile
        if (TRANSB) {
            #pragma unroll
            for (int l = 0; l < 2; l++) {
                int n = arow + l * 64;
                float4 vb = *(const float4*)(B + (size_t)(colBase + n) * ldb + k0 + ac4);
                Bs[ac4 + 0][n] = vb.x;
                Bs[ac4 + 1][n] = vb.y;
                Bs[ac4 + 2][n] = vb.z;
                Bs[ac4 + 3][n] = vb.w;
            }
        } else {
            #pragma unroll
            for (int l = 0; l < 2; l++) {
                int kk = bk + l * 8;
                float4 vb = *(const float4*)(B + (size_t)(k0 + kk) * ldb + colBase + bc);
                *(float4*)&Bs[kk][bc] = vb;
            }
        }
        __syncthreads();

        #pragma unroll
        for (int k = 0; k < BK; k++) {
            float a[8], b[8];
            *(float4*)&a[0] = *(const float4*)&As[k][ty * 4];
            *(float4*)&a[4] = *(const float4*)&As[k][64 + ty * 4];
            *(float4*)&b[0] = *(const float4*)&Bs[k][tx * 4];
            *(float4*)&b[4] = *(const float4*)&Bs[k][64 + tx * 4];
            #pragma unroll
            for (int i = 0; i < 8; i++)
                #pragma unroll
                for (int j = 0; j < 8; j++)
                    acc[i][j] = fmaf(a[i], b[j], acc[i][j]);
        }
        __syncthreads();
    }

    // Epilogue
    #pragma unroll
    for (int i = 0; i < 8; i++) {
        int r = rowBase + ((i < 4) ? (ty * 4 + i) : (64 + ty * 4 + i - 4));
        #pragma unroll
        for (int jj = 0; jj < 2; jj++) {
            int c = colBase + (jj ? (64 + tx * 4) : (tx * 4));
            float4 o;
            o.x = acc[i][jj * 4 + 0] * alpha;
            o.y = acc[i][jj * 4 + 1] * alpha;
            o.z = acc[i][jj * 4 + 2] * alpha;
            o.w = acc[i][jj * 4 + 3] * alpha;
            if (ADDC) {
                float4 ad = *(const float4*)(ADD0 + (size_t)r * ldc + c);
                o.x += ad.x; o.y += ad.y; o.z += ad.z; o.w += ad.w;
            }
            *(float4*)(C + (size_t)r * ldc + c) = o;
        }
    }
}

// ------------------------------------------------------------------
// Host launcher
// ------------------------------------------------------------------
extern "C" void kernel_launch(void* const* d_in, const int* in_sizes, int n_in,
                              void* d_out, int out_size)
{
    const float* hs    = (const float*)d_in[0];
    const float* resid = (const float*)d_in[1];
    const float* cosp  = (const float*)d_in[2];
    const float* sinp  = (const float*)d_in[3];
    const float* w_qkv = (const float*)d_in[4];
    const float* w_o   = (const float*)d_in[5];
    const float* w_gu  = (const float*)d_in[6];
    const float* w_dn  = (const float*)d_in[7];
    const float* ln1   = (const float*)d_in[8];
    const float* ln2   = (const float*)d_in[9];

    float* out     = (float*)d_out;
    float* mlp_out = out;                          // [T, H]
    float* res2    = out + (size_t)Tc * Hc;        // [T, H]

    float *p_res1, *p_normed, *p_qkv, *p_attn, *p_scores, *p_gu, *p_act;
    cudaGetSymbolAddress((void**)&p_res1,   g_res1);
    cudaGetSymbolAddress((void**)&p_normed, g_normed);
    cudaGetSymbolAddress((void**)&p_qkv,    g_qkv);
    cudaGetSymbolAddress((void**)&p_attn,   g_attn);
    cudaGetSymbolAddress((void**)&p_scores, g_scores);
    cudaGetSymbolAddress((void**)&p_gu,     g_gu);
    cudaGetSymbolAddress((void**)&p_act,    g_act);

    // 1) res1 = hs + residual ; normed = RMSNorm(res1) * ln1
    add_rmsnorm_kernel<<<Tc, 256>>>(hs, resid, ln1, p_res1, p_normed);

    // 2) qkv = normed @ w_qkv   [T x 3H]
    sgemm_kernel<false, false, false, false><<<dim3(3 * Hc / 128, Tc / 128, 1), 256>>>(
        p_normed, w_qkv, p_qkv, nullptr,
        Tc, 3 * Hc, Hc, Hc, 3 * Hc, 3 * Hc,
        0, 0, 0, 0, 0, 0, 1.f);

    // 3) RoPE on q,k (in place)
    rope_kernel<<<(Tc * 2 * NHc * HALFc) / 256, 256>>>(p_qkv, cosp, sinp);

    // 4) scores[z] = scale * Q_z @ K_z^T  (causal block-skip)
    sgemm_kernel<true, false, true, false><<<dim3(Sc / 128, Sc / 128, Bc * NHc), 256>>>(
        p_qkv /*Q*/, p_qkv + Hc /*K*/, p_scores, nullptr,
        Sc, Sc, HDc, 3 * Hc, 3 * Hc, Sc,
        (long long)Sc * 3 * Hc, HDc,                 // A strides (batch, head)
        (long long)Sc * 3 * Hc, HDc,                 // B strides
        (long long)NHc * Sc * Sc, (long long)Sc * Sc, // C strides
        SCALEc);

    // 5) causal softmax in place
    softmax_kernel<<<dim3(Sc, Bc * NHc), 256>>>(p_scores);

    // 6) attn[z] = P_z @ V_z  (K loop limited to rowBase+128)
    sgemm_kernel<false, false, false, true><<<dim3(HDc / 128, Sc / 128, Bc * NHc), 256>>>(
        p_scores, p_qkv + 2 * Hc /*V*/, p_attn, nullptr,
        Sc, HDc, Sc, Sc, 3 * Hc, Hc,
        (long long)NHc * Sc * Sc, (long long)Sc * Sc,
        (long long)Sc * 3 * Hc, HDc,
        (long long)Sc * Hc, HDc,
        1.f);

    // 7) res2 = attn @ w_o + res1   (written directly to output)
    sgemm_kernel<false, true, false, false><<<dim3(Hc / 128, Tc / 128, 1), 256>>>(
        p_attn, w_o, res2, p_res1,
        Tc, Hc, Hc, Hc, Hc, Hc,
        0, 0, 0, 0, 0, 0, 1.f);

    // 8) normed2 = RMSNorm(res2) * ln2
    add_rmsnorm_kernel<<<Tc, 256>>>(res2, nullptr, ln2, nullptr, p_normed);

    // 9) gu = normed2 @ w_gate_up   [T x 2I]
    sgemm_kernel<false, false, false, false><<<dim3(2 * Ic / 128, Tc / 128, 1), 256>>>(
        p_normed, w_gu, p_gu, nullptr,
        Tc, 2 * Ic, Hc, Hc, 2 * Ic, 2 * Ic,
        0, 0, 0, 0, 0, 0, 1.f);

    // 10) act = silu(gate) * up
    silu_mul_kernel<<<dim3(Ic / 256, Tc), 256>>>(p_gu, p_act);

    // 11) mlp_out = act @ w_down
    sgemm_kernel<false, false, false, false><<<dim3(Hc / 128, Tc / 128, 1), 256>>>(
        p_act, w_dn, mlp_out, nullptr,
        Tc, Hc, Ic, Ic, Hc, Hc,
        0, 0, 0, 0, 0, 0, 1.f);
}

// round 3
// speedup vs baseline: 1.0509x; 1.0509x over previous
#include <cuda_runtime.h>
#include <math.h>
#include <stdint.h>

// Problem dims (fixed by the dataset)
namespace {
constexpr int Bc  = 2;
constexpr int Sc  = 2048;
constexpr int Hc  = 4096;
constexpr int NHc = 32;
constexpr int HDc = 128;
constexpr int Ic  = 11008;
constexpr int Tc  = Bc * Sc;        // 4096
constexpr int HALFc = HDc / 2;      // 64
constexpr float EPSc = 1e-6f;
constexpr float SCALEc = 0.08838834764831843f; // HD^-0.5
}

// ------------------------------------------------------------------
// Device scratch (static allocation — no cudaMalloc allowed)
// ------------------------------------------------------------------
__device__ float g_res1  [(size_t)Tc * Hc];          //  64 MB
__device__ float g_normed[(size_t)Tc * Hc];          //  64 MB (reused for normed2)
__device__ float g_qkv   [(size_t)Tc * 3 * Hc];      // 192 MB
__device__ float g_attn  [(size_t)Tc * Hc];          //  64 MB
__device__ float g_scores[(size_t)Bc * NHc * Sc * Sc]; // 1 GB (scores, then probs in-place)
__device__ float g_gu    [(size_t)Tc * 2 * Ic];      // 360 MB
__device__ float g_act   [(size_t)Tc * Ic];          // 180 MB

// ------------------------------------------------------------------
// Block reductions (256 threads)
// ------------------------------------------------------------------
__device__ __forceinline__ float block_reduce_sum_256(float v) {
    #pragma unroll
    for (int o = 16; o > 0; o >>= 1) v += __shfl_down_sync(0xffffffffu, v, o);
    __shared__ float red[8];
    int w = threadIdx.x >> 5, l = threadIdx.x & 31;
    if (l == 0) red[w] = v;
    __syncthreads();
    if (w == 0) {
        float x = (l < 8) ? red[l] : 0.f;
        #pragma unroll
        for (int o = 4; o > 0; o >>= 1) x += __shfl_down_sync(0xffu, x, o);
        if (l == 0) red[0] = x;
    }
    __syncthreads();
    float r = red[0];
    __syncthreads();
    return r;
}

__device__ __forceinline__ float block_reduce_max_256(float v) {
    #pragma unroll
    for (int o = 16; o > 0; o >>= 1) v = fmaxf(v, __shfl_down_sync(0xffffffffu, v, o));
    __shared__ float red[8];
    int w = threadIdx.x >> 5, l = threadIdx.x & 31;
    if (l == 0) red[w] = v;
    __syncthreads();
    if (w == 0) {
        float x = (l < 8) ? red[l] : -INFINITY;
        #pragma unroll
        for (int o = 4; o > 0; o >>= 1) x = fmaxf(x, __shfl_down_sync(0xffu, x, o));
        if (l == 0) red[0] = x;
    }
    __syncthreads();
    float r = red[0];
    __syncthreads();
    return r;
}

// ------------------------------------------------------------------
// Fused (optional add) + RMSNorm. One block (256 thr) per row of H=4096.
// If b != nullptr: s = a + b, write s to sum_out. Norm(s)*w -> out.
// ------------------------------------------------------------------
__global__ __launch_bounds__(256) void add_rmsnorm_kernel(
    const float* __restrict__ a, const float* __restrict__ b,
    const float* __restrict__ w, float* __restrict__ sum_out,
    float* __restrict__ out)
{
    int row = blockIdx.x;
    const float4* a4 = (const float4*)(a + (size_t)row * Hc);
    const float4* b4 = b ? (const float4*)(b + (size_t)row * Hc) : nullptr;
    const float4* w4 = (const float4*)w;
    float4* o4 = (float4*)(out + (size_t)row * Hc);
    float4* s4 = sum_out ? (float4*)(sum_out + (size_t)row * Hc) : nullptr;

    float4 v[4];
    float ss = 0.f;
    #pragma unroll
    for (int it = 0; it < 4; it++) {
        int idx = threadIdx.x + it * 256;
        float4 va = a4[idx];
        if (b4) {
            float4 vb = b4[idx];
            va.x += vb.x; va.y += vb.y; va.z += vb.z; va.w += vb.w;
        }
        v[it] = va;
        ss += va.x * va.x + va.y * va.y + va.z * va.z + va.w * va.w;
    }
    float tot = block_reduce_sum_256(ss);
    float scale = rsqrtf(tot / (float)Hc + EPSc);
    #pragma unroll
    for (int it = 0; it < 4; it++) {
        int idx = threadIdx.x + it * 256;
        if (s4) s4[idx] = v[it];
        float4 vw = w4[idx];
        o4[idx] = make_float4(v[it].x * scale * vw.x, v[it].y * scale * vw.y,
                              v[it].z * scale * vw.z, v[it].w * scale * vw.w);
    }
}

// ------------------------------------------------------------------
// RoPE in-place on q and k halves of g_qkv.
// idx -> (t, m(q/k), h, d) ; pair (d, d+64)
// ------------------------------------------------------------------
__global__ __launch_bounds__(256) void rope_kernel(
    float* __restrict__ qkv, const float* __restrict__ cosp,
    const float* __restrict__ sinp)
{
    int idx = blockIdx.x * 256 + threadIdx.x;   // Tc*2*NHc*HALFc = 16,777,216
    int d = idx & (HALFc - 1);
    int h = (idx >> 6) & (NHc - 1);
    int m = (idx >> 11) & 1;
    int t = idx >> 12;
    float* p = qkv + (size_t)t * (3 * Hc) + m * Hc + h * HDc + d;
    float x1 = p[0];
    float x2 = p[HALFc];
    float c = cosp[(size_t)t * HALFc + d];
    float s = sinp[(size_t)t * HALFc + d];
    p[0]     = x1 * c - x2 * s;
    p[HALFc] = x1 * s + x2 * c;
}

// ------------------------------------------------------------------
// Causal softmax in-place on g_scores.
// block = (i row, z = b*NH+h). Reads j<=i, writes probs for j<=i and
// zeros for i < j < rowblock_end (128-aligned) so P@V's K-limit is safe.
// ------------------------------------------------------------------
__global__ __launch_bounds__(256) void softmax_kernel(float* __restrict__ scores)
{
    int i = blockIdx.x;
    int z = blockIdx.y;
    float* row = scores + (size_t)z * Sc * Sc + (size_t)i * Sc;
    int nvalid = i + 1;

    float vals[8];
    float mx = -INFINITY;
    #pragma unroll
    for (int it = 0; it < 8; it++) {
        int j = threadIdx.x + it * 256;
        float v = (j < nvalid) ? row[j] : -INFINITY;
        vals[it] = v;
        mx = fmaxf(mx, v);
    }
    float M = block_reduce_max_256(mx);
    float sum = 0.f;
    #pragma unroll
    for (int it = 0; it < 8; it++) {
        int j = threadIdx.x + it * 256;
        float e = (j < nvalid) ? __expf(vals[it] - M) : 0.f;
        vals[it] = e;
        sum += e;
    }
    float tot = block_reduce_sum_256(sum);
    float inv = 1.f / tot;
    int zero_end = ((i >> 7) + 1) << 7;   // end of this 128-row block
    #pragma unroll
    for (int it = 0; it < 8; it++) {
        int j = threadIdx.x + it * 256;
        if (j < zero_end) row[j] = vals[it] * inv;  // vals==0 for j>i
    }
}

// ------------------------------------------------------------------
// SiLU(gate) * up
// ------------------------------------------------------------------
__global__ __launch_bounds__(256) void silu_mul_kernel(
    const float* __restrict__ gu, float* __restrict__ act)
{
    int t = blockIdx.y;
    int i = blockIdx.x * 256 + threadIdx.x;      // Ic = 43*256
    float g = gu[(size_t)t * (2 * Ic) + i];
    float u = gu[(size_t)t * (2 * Ic) + Ic + i];
    float s = g / (1.f + __expf(-g));
    act[(size_t)t * Ic + i] = s * u;
}

// ------------------------------------------------------------------
// Generic batched SGEMM: C = alpha * A @ op(B) [+ ADD]
// 128x128x16 tiles, 8x8 micro-tiles (split 4+4 for conflict-free LDS),
// 256 threads. Batch via blockIdx.z with (batch, head) strides, heads=NHc.
// TRANSB : B is N x K row-major (C[i,j] = sum_k A[i,k] * B[j,k])
// CAUSAL_SKIP : skip (don't compute/write) blocks fully above diagonal
// KLIMIT : K loop ends at rowBase + 128 (P@V causal truncation)
// ------------------------------------------------------------------
template<bool TRANSB, bool ADDC, bool CAUSAL_SKIP, bool KLIMIT>
__global__ __launch_bounds__(256) void sgemm_kernel(
    const float* __restrict__ A0, const float* __restrict__ B0,
    float* __restrict__ C0, const float* __restrict__ ADD0,
    int M, int N, int K, int lda, int ldb, int ldc,
    long long sAb, long long sAh, long long sBb, long long sBh,
    long long sCb, long long sCh, float alpha)
{
    constexpr int BM = 128, BN = 128, BK = 16;

    int z  = blockIdx.z;
    int zb = z / NHc, zh = z % NHc;
    const float* A = A0 + zb * sAb + zh * sAh;
    const float* B = B0 + zb * sBb + zh * sBh;
    float*       C = C0 + zb * sCb + zh * sCh;

    int rowBase = blockIdx.y * BM;
    int colBase = blockIdx.x * BN;
    if (CAUSAL_SKIP && colBase > rowBase + BM - 1) return;

    int kEnd = KLIMIT ? min(K, rowBase + BM) : K;

    __shared__ float As[BK][BM];
    __shared__ float Bs[BK][BN];

    int tid = threadIdx.x;
    int tx = tid & 15;        // 0..15
    int ty = tid >> 4;        // 0..15

    float acc[8][8];
    #pragma unroll
    for (int i = 0; i < 8; i++)
        #pragma unroll
        for (int j = 0; j < 8; j++) acc[i][j] = 0.f;

    // A-tile (and B-tile when TRANSB) load indices: 128 rows x 16 k
    int arow = tid >> 2;            // 0..63 (+64 on second pass)
    int ac4  = (tid & 3) * 4;       // k offset within tile
    // B-tile NN load indices: 16 k x 128 n
    int bk = tid >> 5;              // 0..7 (+8 on second pass)
    int bc = (tid & 31) * 4;        // n offset within tile

    for (int k0 = 0; k0 < kEnd; k0 += BK) {
        // Load A tile (transposed into As[k][m])
        #pragma unroll
        for (int l = 0; l < 2; l++) {
            int r = arow + l * 64;
            float4 va = *(const float4*)(A + (size_t)(rowBase + r) * lda + k0 + ac4);
            As[ac4 + 0][r] = va.x;
            As[ac4 + 1][r] = va.y;
            As[ac4 + 2][r] = va.z;
            As[ac4 + 3][r] = va.w;
        }
        // Load B tile
        if (TRANSB) {
            #pragma unroll
            for (int l = 0; l < 2; l++) {
                int n = arow + l * 64;
                float4 vb = *(const float4*)(B + (size_t)(colBase + n) * ldb + k0 + ac4);
                Bs[ac4 + 0][n] = vb.x;
                Bs[ac4 + 1][n] = vb.y;
                Bs[ac4 + 2][n] = vb.z;
                Bs[ac4 + 3][n] = vb.w;
            }
        } else {
            #pragma unroll
            for (int l = 0; l < 2; l++) {
                int kk = bk + l * 8;
                float4 vb = *(const float4*)(B + (size_t)(k0 + kk) * ldb + colBase + bc);
                *(float4*)&Bs[kk][bc] = vb;
            }
        }
        __syncthreads();

        #pragma unroll
        for (int k = 0; k < BK; k++) {
            float a[8], b[8];
            *(float4*)&a[0] = *(const float4*)&As[k][ty * 4];
            *(float4*)&a[4] = *(const float4*)&As[k][64 + ty * 4];
            *(float4*)&b[0] = *(const float4*)&Bs[k][tx * 4];
            *(float4*)&b[4] = *(const float4*)&Bs[k][64 + tx * 4];
            #pragma unroll
            for (int i = 0; i < 8; i++)
                #pragma unroll
                for (int j = 0; j < 8; j++)
                    acc[i][j] = fmaf(a[i], b[j], acc[i][j]);
        }
        __syncthreads();
    }

    // Epilogue
    #pragma unroll
    for (int i = 0; i < 8; i++) {
        int r = rowBase + ((i < 4) ? (ty * 4 + i) : (64 + ty * 4 + i - 4));
        #pragma unroll
        for (int jj = 0; jj < 2; jj++) {
            int c = colBase + (jj ? (64 + tx * 4) : (tx * 4));
            float4 o;
            o.x = acc[i][jj * 4 + 0] * alpha;
            o.y = acc[i][jj * 4 + 1] * alpha;
            o.z = acc[i][jj * 4 + 2] * alpha;
            o.w = acc[i][jj * 4 + 3] * alpha;
            if (ADDC) {
                float4 ad = *(const float4*)(ADD0 + (size_t)r * ldc + c);
                o.x += ad.x; o.y += ad.y; o.z += ad.z; o.w += ad.w;
            }
            *(float4*)(C + (size_t)r * ldc + c) = o;
        }
    }
}

// ------------------------------------------------------------------
// Host launcher
// ------------------------------------------------------------------
extern "C" void kernel_launch(void* const* d_in, const int* in_sizes, int n_in,
                              void* d_out, int out_size)
{
    const float* hs    = (const float*)d_in[0];
    const float* resid = (const float*)d_in[1];
    const float* cosp  = (const float*)d_in[2];
    const float* sinp  = (const float*)d_in[3];
    const float* w_qkv = (const float*)d_in[4];
    const float* w_o   = (const float*)d_in[5];
    const float* w_gu  = (const float*)d_in[6];
    const float* w_dn  = (const float*)d_in[7];
    const float* ln1   = (const float*)d_in[8];
    const float* ln2   = (const float*)d_in[9];

    float* out     = (float*)d_out;
    float* mlp_out = out;                          // [T, H]
    float* res2    = out + (size_t)Tc * Hc;        // [T, H]

    float *p_res1, *p_normed, *p_qkv, *p_attn, *p_scores, *p_gu, *p_act;
    cudaGetSymbolAddress((void**)&p_res1,   g_res1);
    cudaGetSymbolAddress((void**)&p_normed, g_normed);
    cudaGetSymbolAddress((void**)&p_qkv,    g_qkv);
    cudaGetSymbolAddress((void**)&p_attn,   g_attn);
    cudaGetSymbolAddress((void**)&p_scores, g_scores);
    cudaGetSymbolAddress((void**)&p_gu,     g_gu);
    cudaGetSymbolAddress((void**)&p_act,    g_act);

    // 1) res1 = hs + residual ; normed = RMSNorm(res1) * ln1
    add_rmsnorm_kernel<<<Tc, 256>>>(hs, resid, ln1, p_res1, p_normed);

    // 2) qkv = normed @ w_qkv   [T x 3H]
    sgemm_kernel<false, false, false, false><<<dim3(3 * Hc / 128, Tc / 128, 1), 256>>>(
        p_normed, w_qkv, p_qkv, nullptr,
        Tc, 3 * Hc, Hc, Hc, 3 * Hc, 3 * Hc,
        0, 0, 0, 0, 0, 0, 1.f);

    // 3) RoPE on q,k (in place)
    rope_kernel<<<(Tc * 2 * NHc * HALFc) / 256, 256>>>(p_qkv, cosp, sinp);

    // 4) scores[z] = scale * Q_z @ K_z^T  (causal block-skip)
    sgemm_kernel<true, false, true, false><<<dim3(Sc / 128, Sc / 128, Bc * NHc), 256>>>(
        p_qkv /*Q*/, p_qkv + Hc /*K*/, p_scores, nullptr,
        Sc, Sc, HDc, 3 * Hc, 3 * Hc, Sc,
        (long long)Sc * 3 * Hc, HDc,                 // A strides (batch, head)
        (long long)Sc * 3 * Hc, HDc,                 // B strides
        (long long)NHc * Sc * Sc, (long long)Sc * Sc, // C strides
        SCALEc);

    // 5) causal softmax in place
    softmax_kernel<<<dim3(Sc, Bc * NHc), 256>>>(p_scores);

    // 6) attn[z] = P_z @ V_z  (K loop limited to rowBase+128)
    sgemm_kernel<false, false, false, true><<<dim3(HDc / 128, Sc / 128, Bc * NHc), 256>>>(
        p_scores, p_qkv + 2 * Hc /*V*/, p_attn, nullptr,
        Sc, HDc, Sc, Sc, 3 * Hc, Hc,
        (long long)NHc * Sc * Sc, (long long)Sc * Sc,
        (long long)Sc * 3 * Hc, HDc,
        (long long)Sc * Hc, HDc,
        1.f);

    // 7) res2 = attn @ w_o + res1   (written directly to output)
    sgemm_kernel<false, true, false, false><<<dim3(Hc / 128, Tc / 128, 1), 256>>>(
        p_attn, w_o, res2, p_res1,
        Tc, Hc, Hc, Hc, Hc, Hc,
        0, 0, 0, 0, 0, 0, 1.f);

    // 8) normed2 = RMSNorm(res2) * ln2
    add_rmsnorm_kernel<<<Tc, 256>>>(res2, nullptr, ln2, nullptr, p_normed);

    // 9) gu = normed2 @ w_gate_up   [T x 2I]
    sgemm_kernel<false, false, false, false><<<dim3(2 * Ic / 128, Tc / 128, 1), 256>>>(
        p_normed, w_gu, p_gu, nullptr,
        Tc, 2 * Ic, Hc, Hc, 2 * Ic, 2 * Ic,
        0, 0, 0, 0, 0, 0, 1.f);

    // 10) act = silu(gate) * up
    silu_mul_kernel<<<dim3(Ic / 256, Tc), 256>>>(p_gu, p_act);

    // 11) mlp_out = act @ w_down
    sgemm_kernel<false, false, false, false><<<dim3(Hc / 128, Tc / 128, 1), 256>>>(
        p_act, w_dn, mlp_out, nullptr,
        Tc, Hc, Ic, Ic, Hc, Hc,
        0, 0, 0, 0, 0, 0, 1.f);
}

// round 5
// speedup vs baseline: 2.2673x; 2.1576x over previous
#include <cuda_runtime.h>
#include <cuda_bf16.h>
#include <math.h>
#include <stdint.h>

namespace {
constexpr int Bc  = 2;
constexpr int Sc  = 2048;
constexpr int Hc  = 4096;
constexpr int NHc = 32;
constexpr int HDc = 128;
constexpr int Ic  = 11008;
constexpr int Tc  = Bc * Sc;
constexpr int HALFc = HDc / 2;
constexpr float EPSc = 1e-6f;
constexpr float SCALEc = 0.08838834764831843f;
}

// ---------------- device scratch ----------------
__device__ float g_res1  [(size_t)Tc * Hc];
__device__ float g_qkv   [(size_t)Tc * 3 * Hc];
__device__ float g_scores[(size_t)Bc * NHc * Sc * Sc];
__device__ float g_gu    [(size_t)Tc * 2 * Ic];

__device__ __nv_bfloat16 g_n_hi [(size_t)Tc * Hc],  g_n_lo [(size_t)Tc * Hc];
__device__ __nv_bfloat16 g_q_hi [(size_t)Tc * Hc],  g_q_lo [(size_t)Tc * Hc];
__device__ __nv_bfloat16 g_k_hi [(size_t)Tc * Hc],  g_k_lo [(size_t)Tc * Hc];
__device__ __nv_bfloat16 g_vt_hi[(size_t)Tc * Hc],  g_vt_lo[(size_t)Tc * Hc];
__device__ __nv_bfloat16 g_p_hi [(size_t)Bc * NHc * Sc * Sc];
__device__ __nv_bfloat16 g_p_lo [(size_t)Bc * NHc * Sc * Sc];
__device__ __nv_bfloat16 g_at_hi[(size_t)Tc * Hc],  g_at_lo[(size_t)Tc * Hc];
__device__ __nv_bfloat16 g_ac_hi[(size_t)Tc * Ic],  g_ac_lo[(size_t)Tc * Ic];
__device__ __nv_bfloat16 g_wqkv_hi[(size_t)Hc * 3 * Hc], g_wqkv_lo[(size_t)Hc * 3 * Hc];
__device__ __nv_bfloat16 g_wo_hi  [(size_t)Hc * Hc],     g_wo_lo  [(size_t)Hc * Hc];
__device__ __nv_bfloat16 g_wgu_hi [(size_t)Hc * 2 * Ic], g_wgu_lo [(size_t)Hc * 2 * Ic];
__device__ __nv_bfloat16 g_wdn_hi [(size_t)Ic * Hc],     g_wdn_lo [(size_t)Ic * Hc];

// ---------------- helpers ----------------
__device__ __forceinline__ uint32_t smem_u32(const void* p) {
    return (uint32_t)__cvta_generic_to_shared(p);
}
__device__ __forceinline__ void ldsm_x4(uint32_t (&r)[4], uint32_t addr) {
    asm volatile("ldmatrix.sync.aligned.m8n8.x4.shared.b16 {%0,%1,%2,%3}, [%4];"
                 : "=r"(r[0]), "=r"(r[1]), "=r"(r[2]), "=r"(r[3]) : "r"(addr));
}
__device__ __forceinline__ void mma_bf16(float (&d)[4], const uint32_t (&a)[4],
                                         uint32_t b0, uint32_t b1) {
    asm volatile("mma.sync.aligned.m16n8k16.row.col.f32.bf16.bf16.f32 "
        "{%0,%1,%2,%3}, {%4,%5,%6,%7}, {%8,%9}, {%0,%1,%2,%3};"
        : "+f"(d[0]), "+f"(d[1]), "+f"(d[2]), "+f"(d[3])
        : "r"(a[0]), "r"(a[1]), "r"(a[2]), "r"(a[3]), "r"(b0), "r"(b1));
}
__device__ __forceinline__ void split2(float v, __nv_bfloat16& h, __nv_bfloat16& l) {
    h = __float2bfloat16(v);
    l = __float2bfloat16(v - __bfloat162float(h));
}

// ---------------- block reductions ----------------
__device__ __forceinline__ float block_reduce_sum_256(float v) {
    #pragma unroll
    for (int o = 16; o > 0; o >>= 1) v += __shfl_down_sync(0xffffffffu, v, o);
    __shared__ float red[8];
    int w = threadIdx.x >> 5, l = threadIdx.x & 31;
    if (l == 0) red[w] = v;
    __syncthreads();
    if (w == 0) {
        float x = (l < 8) ? red[l] : 0.f;
        #pragma unroll
        for (int o = 4; o > 0; o >>= 1) x += __shfl_down_sync(0xffu, x, o);
        if (l == 0) red[0] = x;
    }
    __syncthreads();
    float r = red[0];
    __syncthreads();
    return r;
}
__device__ __forceinline__ float block_reduce_max_256(float v) {
    #pragma unroll
    for (int o = 16; o > 0; o >>= 1) v = fmaxf(v, __shfl_down_sync(0xffffffffu, v, o));
    __shared__ float red[8];
    int w = threadIdx.x >> 5, l = threadIdx.x & 31;
    if (l == 0) red[w] = v;
    __syncthreads();
    if (w == 0) {
        float x = (l < 8) ? red[l] : -INFINITY;
        #pragma unroll
        for (int o = 4; o > 0; o >>= 1) x = fmaxf(x, __shfl_down_sync(0xffu, x, o));
        if (l == 0) red[0] = x;
    }
    __syncthreads();
    float r = red[0];
    __syncthreads();
    return r;
}

// ---------------- add + RMSNorm -> hi/lo ----------------
__global__ __launch_bounds__(256) void add_rmsnorm_kernel(
    const float* __restrict__ a, const float* __restrict__ b,
    const float* __restrict__ w, float* __restrict__ sum_out,
    __nv_bfloat16* __restrict__ ohi, __nv_bfloat16* __restrict__ olo)
{
    int row = blockIdx.x;
    const float4* a4 = (const float4*)(a + (size_t)row * Hc);
    const float4* b4 = b ? (const float4*)(b + (size_t)row * Hc) : nullptr;
    const float4* w4 = (const float4*)w;
    float4* s4 = sum_out ? (float4*)(sum_out + (size_t)row * Hc) : nullptr;
    __nv_bfloat162* oh2 = (__nv_bfloat162*)(ohi + (size_t)row * Hc);
    __nv_bfloat162* ol2 = (__nv_bfloat162*)(olo + (size_t)row * Hc);

    float4 v[4];
    float ss = 0.f;
    #pragma unroll
    for (int it = 0; it < 4; it++) {
        int idx = threadIdx.x + it * 256;
        float4 va = a4[idx];
        if (b4) { float4 vb = b4[idx]; va.x += vb.x; va.y += vb.y; va.z += vb.z; va.w += vb.w; }
        v[it] = va;
        ss += va.x * va.x + va.y * va.y + va.z * va.z + va.w * va.w;
    }
    float tot = block_reduce_sum_256(ss);
    float scale = rsqrtf(tot / (float)Hc + EPSc);
    #pragma unroll
    for (int it = 0; it < 4; it++) {
        int idx = threadIdx.x + it * 256;
        if (s4) s4[idx] = v[it];
        float4 vw = w4[idx];
        float y0 = v[it].x * scale * vw.x, y1 = v[it].y * scale * vw.y;
        float y2 = v[it].z * scale * vw.z, y3 = v[it].w * scale * vw.w;
        __nv_bfloat16 h0,l0,h1,l1,h2,l2,h3,l3;
        split2(y0,h0,l0); split2(y1,h1,l1); split2(y2,h2,l2); split2(y3,h3,l3);
        oh2[idx*2]   = __nv_bfloat162(h0,h1);
        oh2[idx*2+1] = __nv_bfloat162(h2,h3);
        ol2[idx*2]   = __nv_bfloat162(l0,l1);
        ol2[idx*2+1] = __nv_bfloat162(l2,l3);
    }
}

// ---------------- RoPE: fp32 qkv -> Q/K hi/lo ----------------
__global__ __launch_bounds__(256) void rope_kernel(
    const float* __restrict__ qkv, const float* __restrict__ cosp,
    const float* __restrict__ sinp,
    __nv_bfloat16* __restrict__ qhi, __nv_bfloat16* __restrict__ qlo,
    __nv_bfloat16* __restrict__ khi, __nv_bfloat16* __restrict__ klo)
{
    int idx = blockIdx.x * 256 + threadIdx.x;
    int d = idx & (HALFc - 1);
    int h = (idx >> 6) & (NHc - 1);
    int m = (idx >> 11) & 1;
    int t = idx >> 12;
    const float* p = qkv + (size_t)t * (3 * Hc) + m * Hc + h * HDc + d;
    float x1 = p[0], x2 = p[HALFc];
    float c = cosp[(size_t)t * HALFc + d];
    float s = sinp[(size_t)t * HALFc + d];
    float y1 = x1 * c - x2 * s;
    float y2 = x1 * s + x2 * c;
    __nv_bfloat16* dh = (m ? khi : qhi) + (size_t)t * Hc + h * HDc + d;
    __nv_bfloat16* dl = (m ? klo : qlo) + (size_t)t * Hc + h * HDc + d;
    __nv_bfloat16 h1, l1, h2, l2;
    split2(y1, h1, l1); split2(y2, h2, l2);
    dh[0] = h1; dh[HALFc] = h2;
    dl[0] = l1; dl[HALFc] = l2;
}

// ------- transpose fp32 [Y,X] (ld=in_ld) -> hi/lo [X,Y]; batched via z -------
__global__ __launch_bounds__(256) void transpose_convert_kernel(
    const float* __restrict__ in, long long inSb, long long inSh, int in_ld,
    __nv_bfloat16* __restrict__ ohi, __nv_bfloat16* __restrict__ olo,
    long long outSz, int Y)
{
    __shared__ float tile[32][33];
    int z = blockIdx.z, zb = z / NHc, zh = z % NHc;
    const float* inp = in + zb * inSb + zh * inSh;
    __nv_bfloat16* oh = ohi + (long long)z * outSz;
    __nv_bfloat16* ol = olo + (long long)z * outSz;
    int tx = threadIdx.x & 31, ty = threadIdx.x >> 5;
    int gx = blockIdx.x * 32 + tx;
    #pragma unroll
    for (int i = 0; i < 4; i++) {
        int gy = blockIdx.y * 32 + ty + i * 8;
        tile[ty + i * 8][tx] = inp[(size_t)gy * in_ld + gx];
    }
    __syncthreads();
    int ox = blockIdx.y * 32 + tx;
    #pragma unroll
    for (int i = 0; i < 4; i++) {
        int oy = blockIdx.x * 32 + ty + i * 8;
        float v = tile[tx][ty + i * 8];
        __nv_bfloat16 h, l;
        split2(v, h, l);
        oh[(size_t)oy * Y + ox] = h;
        ol[(size_t)oy * Y + ox] = l;
    }
}

// ---------------- causal softmax -> P hi/lo ----------------
__global__ __launch_bounds__(256) void softmax_kernel(
    const float* __restrict__ scores,
    __nv_bfloat16* __restrict__ phi, __nv_bfloat16* __restrict__ plo)
{
    int i = blockIdx.x;
    int z = blockIdx.y;
    const float* row = scores + (size_t)z * Sc * Sc + (size_t)i * Sc;
    __nv_bfloat16* ph = phi + (size_t)z * Sc * Sc + (size_t)i * Sc;
    __nv_bfloat16* pl = plo + (size_t)z * Sc * Sc + (size_t)i * Sc;
    int nvalid = i + 1;

    float vals[8];
    float mx = -INFINITY;
    #pragma unroll
    for (int it = 0; it < 8; it++) {
        int j = threadIdx.x + it * 256;
        float v = (j < nvalid) ? row[j] : -INFINITY;
        vals[it] = v;
        mx = fmaxf(mx, v);
    }
    float M = block_reduce_max_256(mx);
    float sum = 0.f;
    #pragma unroll
    for (int it = 0; it < 8; it++) {
        int j = threadIdx.x + it * 256;
        float e = (j < nvalid) ? __expf(vals[it] - M) : 0.f;
        vals[it] = e;
        sum += e;
    }
    float tot = block_reduce_sum_256(sum);
    float inv = 1.f / tot;
    int zero_end = ((i >> 7) + 1) << 7;
    #pragma unroll
    for (int it = 0; it < 8; it++) {
        int j = threadIdx.x + it * 256;
        if (j < zero_end) {
            float p = vals[it] * inv;
            __nv_bfloat16 h, l;
            split2(p, h, l);
            ph[j] = h; pl[j] = l;
        }
    }
}

// ---------------- SiLU(gate)*up -> hi/lo ----------------
__global__ __launch_bounds__(256) void silu_mul_kernel(
    const float* __restrict__ gu,
    __nv_bfloat16* __restrict__ ahi, __nv_bfloat16* __restrict__ alo)
{
    int t = blockIdx.y;
    int i = blockIdx.x * 256 + threadIdx.x;
    float g = gu[(size_t)t * (2 * Ic) + i];
    float u = gu[(size_t)t * (2 * Ic) + Ic + i];
    float s = g / (1.f + __expf(-g));
    float y = s * u;
    __nv_bfloat16 h, l;
    split2(y, h, l);
    ahi[(size_t)t * Ic + i] = h;
    alo[(size_t)t * Ic + i] = l;
}

// ------------------------------------------------------------------
// HMMA GEMM: C = alpha*(A@B^T)[+ADD]. A:[M,K], B:[N,K] hi/lo K-major
// bf16 planes. BM=BN=128, BK=32. 8 warps, each 32m x 64n.
// 3 passes (hh, hl, lh) accumulate into the same fp32 regs.
// ------------------------------------------------------------------
template<bool CAUSAL, bool KLIM, bool ADDC, bool HILO>
__global__ __launch_bounds__(256, 1) void hmma_gemm_kernel(
    const __nv_bfloat16* __restrict__ Ahi, const __nv_bfloat16* __restrict__ Alo,
    const __nv_bfloat16* __restrict__ Bhi, const __nv_bfloat16* __restrict__ Blo,
    float* __restrict__ Cf, __nv_bfloat16* __restrict__ Chi, __nv_bfloat16* __restrict__ Clo,
    const float* __restrict__ ADDp,
    int K, int lda, int ldb, int ldc,
    long long sAb, long long sAh_, long long sBb, long long sBh_,
    long long sCb, long long sCh_, float alpha)
{
    constexpr int BM = 128, BN = 128, BK = 32;
    constexpr int SROW = 40;                     // bf16 stride (80B, conflict-free+aligned)

    int rowBase = blockIdx.y * BM;
    int colBase = blockIdx.x * BN;
    if (CAUSAL && colBase > rowBase + BM - 1) return;

    __shared__ __nv_bfloat16 sAh[BM * SROW], sAl[BM * SROW];
    __shared__ __nv_bfloat16 sBh[BN * SROW], sBl[BN * SROW];

    int tid = threadIdx.x;
    int wid = tid >> 5, lane = tid & 31;
    int wm = wid & 3, wn = wid >> 2;

    int z = blockIdx.z, zb = z / NHc, zh = z % NHc;
    const __nv_bfloat16* Ah = Ahi + zb * sAb + zh * sAh_;
    const __nv_bfloat16* Al = Alo + zb * sAb + zh * sAh_;
    const __nv_bfloat16* Bh = Bhi + zb * sBb + zh * sBh_;
    const __nv_bfloat16* Bl = Blo + zb * sBb + zh * sBh_;

    int kEnd = KLIM ? min(K, rowBase + BM) : K;
    int nch  = kEnd / BK;

    float acc[2][8][4];
    #pragma unroll
    for (int a = 0; a < 2; a++)
        #pragma unroll
        for (int b = 0; b < 8; b++)
            #pragma unroll
            for (int c = 0; c < 4; c++) acc[a][b][c] = 0.f;

    // gmem load mapping: i = it*256+tid -> row=i>>2, seg=i&3 (8 bf16 per seg)
    int r0 = tid >> 2,          s0 = (tid & 3) * 8;
    int r1 = (256 + tid) >> 2,  s1 = (tid & 3) * 8;
    uint32_t so0 = (uint32_t)(r0 * SROW + s0) * 2;   // smem byte offsets
    uint32_t so1 = (uint32_t)(r1 * SROW + s1) * 2;
    uint32_t sAh_u = smem_u32(sAh), sAl_u = smem_u32(sAl);
    uint32_t sBh_u = smem_u32(sBh), sBl_u = smem_u32(sBl);

    // ldmatrix lane addressing
    int mat = lane >> 3, r8 = lane & 7;
    int a_row = (mat & 1) * 8 + r8, a_k = (mat >> 1) * 8;     // A frags
    int b_n   = (mat >> 1) * 8 + r8, b_k = (mat & 1) * 8;     // B frags

    uint4 pf[8];
    {   // prefetch chunk 0
        const __nv_bfloat16* A0 = Ah + (size_t)(rowBase + r0) * lda + s0;
        const __nv_bfloat16* A1 = Ah + (size_t)(rowBase + r1) * lda + s1;
        pf[0] = *(const uint4*)A0;
        pf[1] = *(const uint4*)(Al + (size_t)(rowBase + r0) * lda + s0);
        pf[2] = *(const uint4*)(Bh + (size_t)(colBase + r0) * ldb + s0);
        pf[3] = *(const uint4*)(Bl + (size_t)(colBase + r0) * ldb + s0);
        pf[4] = *(const uint4*)A1;
        pf[5] = *(const uint4*)(Al + (size_t)(rowBase + r1) * lda + s1);
        pf[6] = *(const uint4*)(Bh + (size_t)(colBase + r1) * ldb + s1);
        pf[7] = *(const uint4*)(Bl + (size_t)(colBase + r1) * ldb + s1);
    }

    for (int c = 0; c < nch; ++c) {
        // store prefetched chunk to smem
        *(uint4*)((char*)sAh + so0) = pf[0];
        *(uint4*)((char*)sAl + so0) = pf[1];
        *(uint4*)((char*)sBh + so0) = pf[2];
        *(uint4*)((char*)sBl + so0) = pf[3];
        *(uint4*)((char*)sAh + so1) = pf[4];
        *(uint4*)((char*)sAl + so1) = pf[5];
        *(uint4*)((char*)sBh + so1) = pf[6];
        *(uint4*)((char*)sBl + so1) = pf[7];
        __syncthreads();

        if (c + 1 < nch) {   // prefetch next chunk
            int k0 = (c + 1) * BK;
            pf[0] = *(const uint4*)(Ah + (size_t)(rowBase + r0) * lda + k0 + s0);
            pf[1] = *(const uint4*)(Al + (size_t)(rowBase + r0) * lda + k0 + s0);
            pf[2] = *(const uint4*)(Bh + (size_t)(colBase + r0) * ldb + k0 + s0);
            pf[3] = *(const uint4*)(Bl + (size_t)(colBase + r0) * ldb + k0 + s0);
            pf[4] = *(const uint4*)(Ah + (size_t)(rowBase + r1) * lda + k0 + s1);
            pf[5] = *(const uint4*)(Al + (size_t)(rowBase + r1) * lda + k0 + s1);
            pf[6] = *(const uint4*)(Bh + (size_t)(colBase + r1) * ldb + k0 + s1);
            pf[7] = *(const uint4*)(Bl + (size_t)(colBase + r1) * ldb + k0 + s1);
        }

        #pragma unroll
        for (int ks = 0; ks < 2; ++ks) {
            uint32_t ah[2][4], al[2][4];
            #pragma unroll
            for (int mt = 0; mt < 2; ++mt) {
                uint32_t off = (uint32_t)((wm * 32 + mt * 16 + a_row) * SROW
                                          + ks * 16 + a_k) * 2;
                ldsm_x4(ah[mt], sAh_u + off);
                ldsm_x4(al[mt], sAl_u + off);
            }
            #pragma unroll
            for (int nt = 0; nt < 4; ++nt) {
                uint32_t boff = (uint32_t)((wn * 64 + nt * 16 + b_n) * SROW
                                           + ks * 16 + b_k) * 2;
                uint32_t bh[4], bl[4];
                ldsm_x4(bh, sBh_u + boff);
                ldsm_x4(bl, sBl_u + boff);
                #pragma unroll
                for (int mt = 0; mt < 2; ++mt) {
                    #pragma unroll
                    for (int h2 = 0; h2 < 2; ++h2) {
                        mma_bf16(acc[mt][nt*2+h2], ah[mt], bh[2*h2], bh[2*h2+1]);
                        mma_bf16(acc[mt][nt*2+h2], ah[mt], bl[2*h2], bl[2*h2+1]);
                        mma_bf16(acc[mt][nt*2+h2], al[mt], bh[2*h2], bh[2*h2+1]);
                    }
                }
            }
        }
        __syncthreads();
    }

    // ---------------- epilogue ----------------
    float*         Cfz = Cf  ? Cf  + zb * sCb + zh * sCh_ : nullptr;
    __nv_bfloat16* Chz = Chi ? Chi + zb * sCb + zh * sCh_ : nullptr;
    __nv_bfloat16* Clz = Clo ? Clo + zb * sCb + zh * sCh_ : nullptr;
    const float*   ADz = ADDp ? ADDp + zb * sCb + zh * sCh_ : nullptr;

    #pragma unroll
    for (int mt = 0; mt < 2; ++mt) {
        int r = rowBase + wm * 32 + mt * 16 + (lane >> 2);
        #pragma unroll
        for (int j8 = 0; j8 < 8; ++j8) {
            int cc = colBase + wn * 64 + j8 * 8 + 2 * (lane & 3);
            float v0 = acc[mt][j8][0] * alpha;
            float v1 = acc[mt][j8][1] * alpha;
            float v2 = acc[mt][j8][2] * alpha;
            float v3 = acc[mt][j8][3] * alpha;
            if (ADDC) {
                float2 a0 = *(const float2*)(ADz + (size_t)r * ldc + cc);
                float2 a1 = *(const float2*)(ADz + (size_t)(r + 8) * ldc + cc);
                v0 += a0.x; v1 += a0.y; v2 += a1.x; v3 += a1.y;
            }
            if (!HILO) {
                *(float2*)(Cfz + (size_t)r * ldc + cc)       = make_float2(v0, v1);
                *(float2*)(Cfz + (size_t)(r + 8) * ldc + cc) = make_float2(v2, v3);
            } else {
                __nv_bfloat16 h0,l0,h1,l1,h2,l2,h3,l3;
                split2(v0,h0,l0); split2(v1,h1,l1);
                split2(v2,h2,l2); split2(v3,h3,l3);
                *(__nv_bfloat162*)(Chz + (size_t)r * ldc + cc)       = __nv_bfloat162(h0,h1);
                *(__nv_bfloat162*)(Clz + (size_t)r * ldc + cc)       = __nv_bfloat162(l0,l1);
                *(__nv_bfloat162*)(Chz + (size_t)(r + 8) * ldc + cc) = __nv_bfloat162(h2,h3);
                *(__nv_bfloat162*)(Clz + (size_t)(r + 8) * ldc + cc) = __nv_bfloat162(l2,l3);
            }
        }
    }
}

// ---------------- host launcher ----------------
extern "C" void kernel_launch(void* const* d_in, const int* in_sizes, int n_in,
                              void* d_out, int out_size)
{
    const float* hs    = (const float*)d_in[0];
    const float* resid = (const float*)d_in[1];
    const float* cosp  = (const float*)d_in[2];
    const float* sinp  = (const float*)d_in[3];
    const float* w_qkv = (const float*)d_in[4];
    const float* w_o   = (const float*)d_in[5];
    const float* w_gu  = (const float*)d_in[6];
    const float* w_dn  = (const float*)d_in[7];
    const float* ln1   = (const float*)d_in[8];
    const float* ln2   = (const float*)d_in[9];

    float* out     = (float*)d_out;
    float* mlp_out = out;
    float* res2    = out + (size_t)Tc * Hc;

    float *p_res1, *p_qkv, *p_scores, *p_gu;
    cudaGetSymbolAddress((void**)&p_res1,   g_res1);
    cudaGetSymbolAddress((void**)&p_qkv,    g_qkv);
    cudaGetSymbolAddress((void**)&p_scores, g_scores);
    cudaGetSymbolAddress((void**)&p_gu,     g_gu);
    __nv_bfloat16 *nh,*nl,*qh,*ql,*kh,*kl,*vth,*vtl,*ph,*pl,*ath,*atl,*ach,*acl;
    __nv_bfloat16 *wqh,*wql,*woh,*wol,*wgh,*wgl,*wdh,*wdl;
    cudaGetSymbolAddress((void**)&nh,  g_n_hi);  cudaGetSymbolAddress((void**)&nl,  g_n_lo);
    cudaGetSymbolAddress((void**)&qh,  g_q_hi);  cudaGetSymbolAddress((void**)&ql,  g_q_lo);
    cudaGetSymbolAddress((void**)&kh,  g_k_hi);  cudaGetSymbolAddress((void**)&kl,  g_k_lo);
    cudaGetSymbolAddress((void**)&vth, g_vt_hi); cudaGetSymbolAddress((void**)&vtl, g_vt_lo);
    cudaGetSymbolAddress((void**)&ph,  g_p_hi);  cudaGetSymbolAddress((void**)&pl,  g_p_lo);
    cudaGetSymbolAddress((void**)&ath, g_at_hi); cudaGetSymbolAddress((void**)&atl, g_at_lo);
    cudaGetSymbolAddress((void**)&ach, g_ac_hi); cudaGetSymbolAddress((void**)&acl, g_ac_lo);
    cudaGetSymbolAddress((void**)&wqh, g_wqkv_hi); cudaGetSymbolAddress((void**)&wql, g_wqkv_lo);
    cudaGetSymbolAddress((void**)&woh, g_wo_hi);   cudaGetSymbolAddress((void**)&wol, g_wo_lo);
    cudaGetSymbolAddress((void**)&wgh, g_wgu_hi);  cudaGetSymbolAddress((void**)&wgl, g_wgu_lo);
    cudaGetSymbolAddress((void**)&wdh, g_wdn_hi);  cudaGetSymbolAddress((void**)&wdl, g_wdn_lo);

    // weight transposes + hi/lo conversion
    transpose_convert_kernel<<<dim3(3*Hc/32, Hc/32, 1), 256>>>(w_qkv, 0, 0, 3*Hc, wqh, wql, 0, Hc);
    transpose_convert_kernel<<<dim3(Hc/32,   Hc/32, 1), 256>>>(w_o,   0, 0, Hc,   woh, wol, 0, Hc);
    transpose_convert_kernel<<<dim3(2*Ic/32, Hc/32, 1), 256>>>(w_gu,  0, 0, 2*Ic, wgh, wgl, 0, Hc);
    transpose_convert_kernel<<<dim3(Hc/32,   Ic/32, 1), 256>>>(w_dn,  0, 0, Hc,   wdh, wdl, 0, Ic);

    // 1) res1 + RMSNorm -> n planes
    add_rmsnorm_kernel<<<Tc, 256>>>(hs, resid, ln1, p_res1, nh, nl);

    // 2) qkv = normed @ w_qkv (fp32)
    hmma_gemm_kernel<false,false,false,false><<<dim3(3*Hc/128, Tc/128, 1), 256>>>(
        nh, nl, wqh, wql, p_qkv, nullptr, nullptr, nullptr,
        Hc, Hc, Hc, 3*Hc, 0,0,0,0,0,0, 1.f);

    // 3) RoPE -> q/k planes
    rope_kernel<<<(Tc*2*NHc*HALFc)/256, 256>>>(p_qkv, cosp, sinp, qh, ql, kh, kl);

    // 3b) V transpose -> vt planes [z][HD][S]
    transpose_convert_kernel<<<dim3(HDc/32, Sc/32, Bc*NHc), 256>>>(
        p_qkv + 2*Hc, (long long)Sc*3*Hc, HDc, 3*Hc, vth, vtl, (long long)HDc*Sc, Sc);

    // 4) scores = scale * Q @ K^T (causal skip)
    hmma_gemm_kernel<true,false,false,false><<<dim3(Sc/128, Sc/128, Bc*NHc), 256>>>(
        qh, ql, kh, kl, p_scores, nullptr, nullptr, nullptr,
        HDc, Hc, Hc, Sc,
        (long long)Sc*Hc, HDc, (long long)Sc*Hc, HDc,
        (long long)NHc*Sc*Sc, (long long)Sc*Sc, SCALEc);

    // 5) softmax -> P planes
    softmax_kernel<<<dim3(Sc, Bc*NHc), 256>>>(p_scores, ph, pl);

    // 6) attn = P @ V (K-limited) -> at planes (hi/lo)
    hmma_gemm_kernel<false,true,false,true><<<dim3(1, Sc/128, Bc*NHc), 256>>>(
        ph, pl, vth, vtl, nullptr, ath, atl, nullptr,
        Sc, Sc, Sc, Hc,
        (long long)NHc*Sc*Sc, (long long)Sc*Sc,
        (long long)NHc*HDc*Sc, (long long)HDc*Sc,
        (long long)Sc*Hc, HDc, 1.f);

    // 7) res2 = attn @ w_o + res1 (fp32, into output)
    hmma_gemm_kernel<false,false,true,false><<<dim3(Hc/128, Tc/128, 1), 256>>>(
        ath, atl, woh, wol, res2, nullptr, nullptr, p_res1,
        Hc, Hc, Hc, Hc, 0,0,0,0,0,0, 1.f);

    // 8) RMSNorm(res2) -> n planes
    add_rmsnorm_kernel<<<Tc, 256>>>(res2, nullptr, ln2, nullptr, nh, nl);

    // 9) gu = normed2 @ w_gate_up (fp32)
    hmma_gemm_kernel<false,false,false,false><<<dim3(2*Ic/128, Tc/128, 1), 256>>>(
        nh, nl, wgh, wgl, p_gu, nullptr, nullptr, nullptr,
        Hc, Hc, Hc, 2*Ic, 0,0,0,0,0,0, 1.f);

    // 10) silu*up -> ac planes
    silu_mul_kernel<<<dim3(Ic/256, Tc), 256>>>(p_gu, ach, acl);

    // 11) mlp_out = act @ w_down (fp32, into output)
    hmma_gemm_kernel<false,false,false,false><<<dim3(Hc/128, Tc/128, 1), 256>>>(
        ach, acl, wdh, wdl, mlp_out, nullptr, nullptr, nullptr,
        Ic, Ic, Ic, Hc, 0,0,0,0,0,0, 1.f);
}

// round 6
// speedup vs baseline: 2.3373x; 1.0309x over previous
#include <cuda_runtime.h>
#include <cuda_bf16.h>
#include <math.h>
#include <stdint.h>

namespace {
constexpr int Bc  = 2;
constexpr int Sc  = 2048;
constexpr int Hc  = 4096;
constexpr int NHc = 32;
constexpr int HDc = 128;
constexpr int Ic  = 11008;
constexpr int Tc  = Bc * Sc;
constexpr int HALFc = HDc / 2;
constexpr float EPSc = 1e-6f;
constexpr float SCALEc = 0.08838834764831843f;
}

// ---------------- device scratch ----------------
__device__ float g_res1  [(size_t)Tc * Hc];
__device__ float g_qkv   [(size_t)Tc * 3 * Hc];
__device__ float g_scores[(size_t)Bc * NHc * Sc * Sc];
__device__ float g_gu    [(size_t)Tc * 2 * Ic];

__device__ __nv_bfloat16 g_n_hi [(size_t)Tc * Hc],  g_n_lo [(size_t)Tc * Hc];
__device__ __nv_bfloat16 g_q_hi [(size_t)Tc * Hc],  g_q_lo [(size_t)Tc * Hc];
__device__ __nv_bfloat16 g_k_hi [(size_t)Tc * Hc],  g_k_lo [(size_t)Tc * Hc];
__device__ __nv_bfloat16 g_vt_hi[(size_t)Tc * Hc],  g_vt_lo[(size_t)Tc * Hc];
__device__ __nv_bfloat16 g_p_hi [(size_t)Bc * NHc * Sc * Sc];
__device__ __nv_bfloat16 g_p_lo [(size_t)Bc * NHc * Sc * Sc];
__device__ __nv_bfloat16 g_at_hi[(size_t)Tc * Hc],  g_at_lo[(size_t)Tc * Hc];
__device__ __nv_bfloat16 g_ac_hi[(size_t)Tc * Ic],  g_ac_lo[(size_t)Tc * Ic];
__device__ __nv_bfloat16 g_wqkv_hi[(size_t)Hc * 3 * Hc], g_wqkv_lo[(size_t)Hc * 3 * Hc];
__device__ __nv_bfloat16 g_wo_hi  [(size_t)Hc * Hc],     g_wo_lo  [(size_t)Hc * Hc];
__device__ __nv_bfloat16 g_wgu_hi [(size_t)Hc * 2 * Ic], g_wgu_lo [(size_t)Hc * 2 * Ic];
__device__ __nv_bfloat16 g_wdn_hi [(size_t)Ic * Hc],     g_wdn_lo [(size_t)Ic * Hc];

// ---------------- helpers ----------------
__device__ __forceinline__ uint32_t smem_u32(const void* p) {
    return (uint32_t)__cvta_generic_to_shared(p);
}
__device__ __forceinline__ void ldsm_x4(uint32_t (&r)[4], uint32_t addr) {
    asm volatile("ldmatrix.sync.aligned.m8n8.x4.shared.b16 {%0,%1,%2,%3}, [%4];"
                 : "=r"(r[0]), "=r"(r[1]), "=r"(r[2]), "=r"(r[3]) : "r"(addr));
}
__device__ __forceinline__ void mma_bf16(float (&d)[4], const uint32_t (&a)[4],
                                         uint32_t b0, uint32_t b1) {
    asm volatile("mma.sync.aligned.m16n8k16.row.col.f32.bf16.bf16.f32 "
        "{%0,%1,%2,%3}, {%4,%5,%6,%7}, {%8,%9}, {%0,%1,%2,%3};"
        : "+f"(d[0]), "+f"(d[1]), "+f"(d[2]), "+f"(d[3])
        : "r"(a[0]), "r"(a[1]), "r"(a[2]), "r"(a[3]), "r"(b0), "r"(b1));
}
__device__ __forceinline__ void cp_async16(uint32_t dst, const void* src) {
    asm volatile("cp.async.cg.shared.global [%0], [%1], 16;" :: "r"(dst), "l"(src));
}
#define CP_COMMIT() asm volatile("cp.async.commit_group;" ::: "memory")
#define CP_WAIT(n)  asm volatile("cp.async.wait_group %0;" :: "n"(n) : "memory")
__device__ __forceinline__ void split2(float v, __nv_bfloat16& h, __nv_bfloat16& l) {
    h = __float2bfloat16(v);
    l = __float2bfloat16(v - __bfloat162float(h));
}

// ---------------- block reductions ----------------
__device__ __forceinline__ float block_reduce_sum_256(float v) {
    #pragma unroll
    for (int o = 16; o > 0; o >>= 1) v += __shfl_down_sync(0xffffffffu, v, o);
    __shared__ float red[8];
    int w = threadIdx.x >> 5, l = threadIdx.x & 31;
    if (l == 0) red[w] = v;
    __syncthreads();
    if (w == 0) {
        float x = (l < 8) ? red[l] : 0.f;
        #pragma unroll
        for (int o = 4; o > 0; o >>= 1) x += __shfl_down_sync(0xffu, x, o);
        if (l == 0) red[0] = x;
    }
    __syncthreads();
    float r = red[0];
    __syncthreads();
    return r;
}
__device__ __forceinline__ float block_reduce_max_256(float v) {
    #pragma unroll
    for (int o = 16; o > 0; o >>= 1) v = fmaxf(v, __shfl_down_sync(0xffffffffu, v, o));
    __shared__ float red[8];
    int w = threadIdx.x >> 5, l = threadIdx.x & 31;
    if (l == 0) red[w] = v;
    __syncthreads();
    if (w == 0) {
        float x = (l < 8) ? red[l] : -INFINITY;
        #pragma unroll
        for (int o = 4; o > 0; o >>= 1) x = fmaxf(x, __shfl_down_sync(0xffu, x, o));
        if (l == 0) red[0] = x;
    }
    __syncthreads();
    float r = red[0];
    __syncthreads();
    return r;
}

// ---------------- add + RMSNorm -> hi/lo ----------------
__global__ __launch_bounds__(256) void add_rmsnorm_kernel(
    const float* __restrict__ a, const float* __restrict__ b,
    const float* __restrict__ w, float* __restrict__ sum_out,
    __nv_bfloat16* __restrict__ ohi, __nv_bfloat16* __restrict__ olo)
{
    int row = blockIdx.x;
    const float4* a4 = (const float4*)(a + (size_t)row * Hc);
    const float4* b4 = b ? (const float4*)(b + (size_t)row * Hc) : nullptr;
    const float4* w4 = (const float4*)w;
    float4* s4 = sum_out ? (float4*)(sum_out + (size_t)row * Hc) : nullptr;
    __nv_bfloat162* oh2 = (__nv_bfloat162*)(ohi + (size_t)row * Hc);
    __nv_bfloat162* ol2 = (__nv_bfloat162*)(olo + (size_t)row * Hc);

    float4 v[4];
    float ss = 0.f;
    #pragma unroll
    for (int it = 0; it < 4; it++) {
        int idx = threadIdx.x + it * 256;
        float4 va = a4[idx];
        if (b4) { float4 vb = b4[idx]; va.x += vb.x; va.y += vb.y; va.z += vb.z; va.w += vb.w; }
        v[it] = va;
        ss += va.x * va.x + va.y * va.y + va.z * va.z + va.w * va.w;
    }
    float tot = block_reduce_sum_256(ss);
    float scale = rsqrtf(tot / (float)Hc + EPSc);
    #pragma unroll
    for (int it = 0; it < 4; it++) {
        int idx = threadIdx.x + it * 256;
        if (s4) s4[idx] = v[it];
        float4 vw = w4[idx];
        float y0 = v[it].x * scale * vw.x, y1 = v[it].y * scale * vw.y;
        float y2 = v[it].z * scale * vw.z, y3 = v[it].w * scale * vw.w;
        __nv_bfloat16 h0,l0,h1,l1,h2,l2,h3,l3;
        split2(y0,h0,l0); split2(y1,h1,l1); split2(y2,h2,l2); split2(y3,h3,l3);
        oh2[idx*2]   = __nv_bfloat162(h0,h1);
        oh2[idx*2+1] = __nv_bfloat162(h2,h3);
        ol2[idx*2]   = __nv_bfloat162(l0,l1);
        ol2[idx*2+1] = __nv_bfloat162(l2,l3);
    }
}

// ---------------- RoPE: fp32 qkv -> Q/K hi/lo ----------------
__global__ __launch_bounds__(256) void rope_kernel(
    const float* __restrict__ qkv, const float* __restrict__ cosp,
    const float* __restrict__ sinp,
    __nv_bfloat16* __restrict__ qhi, __nv_bfloat16* __restrict__ qlo,
    __nv_bfloat16* __restrict__ khi, __nv_bfloat16* __restrict__ klo)
{
    int idx = blockIdx.x * 256 + threadIdx.x;
    int d = idx & (HALFc - 1);
    int h = (idx >> 6) & (NHc - 1);
    int m = (idx >> 11) & 1;
    int t = idx >> 12;
    const float* p = qkv + (size_t)t * (3 * Hc) + m * Hc + h * HDc + d;
    float x1 = p[0], x2 = p[HALFc];
    float c = cosp[(size_t)t * HALFc + d];
    float s = sinp[(size_t)t * HALFc + d];
    float y1 = x1 * c - x2 * s;
    float y2 = x1 * s + x2 * c;
    __nv_bfloat16* dh = (m ? khi : qhi) + (size_t)t * Hc + h * HDc + d;
    __nv_bfloat16* dl = (m ? klo : qlo) + (size_t)t * Hc + h * HDc + d;
    __nv_bfloat16 h1, l1, h2, l2;
    split2(y1, h1, l1); split2(y2, h2, l2);
    dh[0] = h1; dh[HALFc] = h2;
    dl[0] = l1; dl[HALFc] = l2;
}

// ------- transpose fp32 [Y,X] (ld=in_ld) -> hi/lo [X,Y]; batched via z -------
__global__ __launch_bounds__(256) void transpose_convert_kernel(
    const float* __restrict__ in, long long inSb, long long inSh, int in_ld,
    __nv_bfloat16* __restrict__ ohi, __nv_bfloat16* __restrict__ olo,
    long long outSz, int Y)
{
    __shared__ float tile[32][33];
    int z = blockIdx.z, zb = z / NHc, zh = z % NHc;
    const float* inp = in + zb * inSb + zh * inSh;
    __nv_bfloat16* oh = ohi + (long long)z * outSz;
    __nv_bfloat16* ol = olo + (long long)z * outSz;
    int tx = threadIdx.x & 31, ty = threadIdx.x >> 5;
    int gx = blockIdx.x * 32 + tx;
    #pragma unroll
    for (int i = 0; i < 4; i++) {
        int gy = blockIdx.y * 32 + ty + i * 8;
        tile[ty + i * 8][tx] = inp[(size_t)gy * in_ld + gx];
    }
    __syncthreads();
    int ox = blockIdx.y * 32 + tx;
    #pragma unroll
    for (int i = 0; i < 4; i++) {
        int oy = blockIdx.x * 32 + ty + i * 8;
        float v = tile[tx][ty + i * 8];
        __nv_bfloat16 h, l;
        split2(v, h, l);
        oh[(size_t)oy * Y + ox] = h;
        ol[(size_t)oy * Y + ox] = l;
    }
}

// ------- causal softmax -> P hi/lo (zero-fill to 256-aligned edge) -------
__global__ __launch_bounds__(256) void softmax_kernel(
    const float* __restrict__ scores,
    __nv_bfloat16* __restrict__ phi, __nv_bfloat16* __restrict__ plo)
{
    int i = blockIdx.x;
    int z = blockIdx.y;
    const float* row = scores + (size_t)z * Sc * Sc + (size_t)i * Sc;
    __nv_bfloat16* ph = phi + (size_t)z * Sc * Sc + (size_t)i * Sc;
    __nv_bfloat16* pl = plo + (size_t)z * Sc * Sc + (size_t)i * Sc;
    int nvalid = i + 1;

    float vals[8];
    float mx = -INFINITY;
    #pragma unroll
    for (int it = 0; it < 8; it++) {
        int j = threadIdx.x + it * 256;
        float v = (j < nvalid) ? row[j] : -INFINITY;
        vals[it] = v;
        mx = fmaxf(mx, v);
    }
    float M = block_reduce_max_256(mx);
    float sum = 0.f;
    #pragma unroll
    for (int it = 0; it < 8; it++) {
        int j = threadIdx.x + it * 256;
        float e = (j < nvalid) ? __expf(vals[it] - M) : 0.f;
        vals[it] = e;
        sum += e;
    }
    float tot = block_reduce_sum_256(sum);
    float inv = 1.f / tot;
    int zero_end = ((i >> 8) + 1) << 8;   // 256-aligned (matches PV BM=256 K-limit)
    #pragma unroll
    for (int it = 0; it < 8; it++) {
        int j = threadIdx.x + it * 256;
        if (j < zero_end) {
            float p = vals[it] * inv;
            __nv_bfloat16 h, l;
            split2(p, h, l);
            ph[j] = h; pl[j] = l;
        }
    }
}

// ---------------- SiLU(gate)*up -> hi/lo ----------------
__global__ __launch_bounds__(256) void silu_mul_kernel(
    const float* __restrict__ gu,
    __nv_bfloat16* __restrict__ ahi, __nv_bfloat16* __restrict__ alo)
{
    int t = blockIdx.y;
    int i = blockIdx.x * 256 + threadIdx.x;
    float g = gu[(size_t)t * (2 * Ic) + i];
    float u = gu[(size_t)t * (2 * Ic) + Ic + i];
    float s = g / (1.f + __expf(-g));
    float y = s * u;
    __nv_bfloat16 h, l;
    split2(y, h, l);
    ahi[(size_t)t * Ic + i] = h;
    alo[(size_t)t * Ic + i] = l;
}

// ------------------------------------------------------------------
// HMMA GEMM: C = alpha*(A@B^T)[+ADD]. A:[M,K], B:[N,K] hi/lo K-major
// bf16 planes. BM=256, BN=128, BK=32. 8 warps, 64x64 warp tiles
// (mt=nt=4, balanced ldsm/mma). cp.async 2-stage pipeline.
// 3 passes (hh, hl, lh) into shared fp32 accumulators.
// ------------------------------------------------------------------
namespace gk {
constexpr int BM = 256, BN = 128, BK = 32, SROW = 40;
constexpr int AOFF_L = BM * SROW * 2;           // 20480
constexpr int BOFF_H = 2 * AOFF_L;              // 40960
constexpr int BOFF_L = BOFF_H + BN * SROW * 2;  // 51200
constexpr int STAGE  = BOFF_L + BN * SROW * 2;  // 61440
constexpr int SMEM_SZ = 2 * STAGE;              // 122880
}

template<bool CAUSAL, bool KLIM, bool ADDC, bool HILO>
__global__ __launch_bounds__(256, 1) void hmma_gemm_kernel(
    const __nv_bfloat16* __restrict__ Ahi, const __nv_bfloat16* __restrict__ Alo,
    const __nv_bfloat16* __restrict__ Bhi, const __nv_bfloat16* __restrict__ Blo,
    float* __restrict__ Cf, __nv_bfloat16* __restrict__ Chi, __nv_bfloat16* __restrict__ Clo,
    const float* __restrict__ ADDp,
    int K, int lda, int ldb, int ldc,
    long long sAb, long long sAh_, long long sBb, long long sBh_,
    long long sCb, long long sCh_, float alpha)
{
    using namespace gk;
    int rowBase = blockIdx.y * BM;
    int colBase = blockIdx.x * BN;
    if (CAUSAL && colBase > rowBase + BM - 1) return;

    extern __shared__ __nv_bfloat16 smem[];
    uint32_t sbase = smem_u32(smem);

    int tid = threadIdx.x;
    int wid = tid >> 5, lane = tid & 31;
    int wm = wid & 3, wn = wid >> 2;          // 4 x 2 warp grid, 64x64 tiles

    int z = blockIdx.z, zb = z / NHc, zh = z % NHc;
    const __nv_bfloat16* Ah = Ahi + zb * sAb + zh * sAh_;
    const __nv_bfloat16* Al = Alo + zb * sAb + zh * sAh_;
    const __nv_bfloat16* Bh = Bhi + zb * sBb + zh * sBh_;
    const __nv_bfloat16* Bl = Blo + zb * sBb + zh * sBh_;

    int kEnd = KLIM ? min(K, rowBase + BM) : K;
    int nch  = kEnd / BK;

    float acc[4][8][4];
    #pragma unroll
    for (int a = 0; a < 4; a++)
        #pragma unroll
        for (int b = 0; b < 8; b++)
            #pragma unroll
            for (int c = 0; c < 4; c++) acc[a][b][c] = 0.f;

    // cp.async mapping: i -> row=i>>2, 16B seg=(i&3)*8 elems
    int ar = tid >> 2, sg = (tid & 3) * 8;
    uint32_t soff = (uint32_t)(ar * SROW + sg) * 2;

    auto issue = [&](int c, int s) {
        int k0 = c * BK;
        uint32_t st = sbase + s * STAGE;
        #pragma unroll
        for (int it = 0; it < 4; it++) {
            int r = ar + it * 64;
            uint32_t o = soff + (uint32_t)(it * 64 * SROW) * 2;
            cp_async16(st + o,          Ah + (size_t)(rowBase + r) * lda + k0 + sg);
            cp_async16(st + AOFF_L + o, Al + (size_t)(rowBase + r) * lda + k0 + sg);
        }
        #pragma unroll
        for (int it = 0; it < 2; it++) {
            int r = ar + it * 64;
            uint32_t o = soff + (uint32_t)(it * 64 * SROW) * 2;
            cp_async16(st + BOFF_H + o, Bh + (size_t)(colBase + r) * ldb + k0 + sg);
            cp_async16(st + BOFF_L + o, Bl + (size_t)(colBase + r) * ldb + k0 + sg);
        }
    };

    // ldmatrix lane addressing
    int mat = lane >> 3, r8 = lane & 7;
    int a_row = (mat & 1) * 8 + r8, a_k = (mat >> 1) * 8;
    int b_n   = (mat >> 1) * 8 + r8, b_k = (mat & 1) * 8;

    issue(0, 0); CP_COMMIT();

    for (int c = 0; c < nch; ++c) {
        if (c + 1 < nch) { issue(c + 1, (c + 1) & 1); CP_COMMIT(); CP_WAIT(1); }
        else             { CP_WAIT(0); }
        __syncthreads();

        uint32_t st = sbase + (c & 1) * STAGE;
        #pragma unroll
        for (int ks = 0; ks < 2; ++ks) {
            uint32_t ah[4][4], al[4][4];
            #pragma unroll
            for (int mt = 0; mt < 4; ++mt) {
                uint32_t off = (uint32_t)((wm * 64 + mt * 16 + a_row) * SROW
                                          + ks * 16 + a_k) * 2;
                ldsm_x4(ah[mt], st + off);
                ldsm_x4(al[mt], st + AOFF_L + off);
            }
            #pragma unroll
            for (int nt = 0; nt < 4; ++nt) {
                uint32_t boff = (uint32_t)((wn * 64 + nt * 16 + b_n) * SROW
                                           + ks * 16 + b_k) * 2;
                uint32_t bh[4], bl[4];
                ldsm_x4(bh, st + BOFF_H + boff);
                ldsm_x4(bl, st + BOFF_L + boff);
                #pragma unroll
                for (int mt = 0; mt < 4; ++mt) {
                    #pragma unroll
                    for (int h2 = 0; h2 < 2; ++h2) {
                        mma_bf16(acc[mt][nt*2+h2], ah[mt], bh[2*h2], bh[2*h2+1]);
                        mma_bf16(acc[mt][nt*2+h2], ah[mt], bl[2*h2], bl[2*h2+1]);
                        mma_bf16(acc[mt][nt*2+h2], al[mt], bh[2*h2], bh[2*h2+1]);
                    }
                }
            }
        }
        __syncthreads();
    }

    // ---------------- epilogue ----------------
    float*         Cfz = Cf  ? Cf  + zb * sCb + zh * sCh_ : nullptr;
    __nv_bfloat16* Chz = Chi ? Chi + zb * sCb + zh * sCh_ : nullptr;
    __nv_bfloat16* Clz = Clo ? Clo + zb * sCb + zh * sCh_ : nullptr;
    const float*   ADz = ADDp ? ADDp + zb * sCb + zh * sCh_ : nullptr;

    #pragma unroll
    for (int mt = 0; mt < 4; ++mt) {
        int r = rowBase + wm * 64 + mt * 16 + (lane >> 2);
        #pragma unroll
        for (int j8 = 0; j8 < 8; ++j8) {
            int cc = colBase + wn * 64 + j8 * 8 + 2 * (lane & 3);
            float v0 = acc[mt][j8][0] * alpha;
            float v1 = acc[mt][j8][1] * alpha;
            float v2 = acc[mt][j8][2] * alpha;
            float v3 = acc[mt][j8][3] * alpha;
            if (ADDC) {
                float2 a0 = *(const float2*)(ADz + (size_t)r * ldc + cc);
                float2 a1 = *(const float2*)(ADz + (size_t)(r + 8) * ldc + cc);
                v0 += a0.x; v1 += a0.y; v2 += a1.x; v3 += a1.y;
            }
            if (!HILO) {
                *(float2*)(Cfz + (size_t)r * ldc + cc)       = make_float2(v0, v1);
                *(float2*)(Cfz + (size_t)(r + 8) * ldc + cc) = make_float2(v2, v3);
            } else {
                __nv_bfloat16 h0,l0,h1,l1,h2,l2,h3,l3;
                split2(v0,h0,l0); split2(v1,h1,l1);
                split2(v2,h2,l2); split2(v3,h3,l3);
                *(__nv_bfloat162*)(Chz + (size_t)r * ldc + cc)       = __nv_bfloat162(h0,h1);
                *(__nv_bfloat162*)(Clz + (size_t)r * ldc + cc)       = __nv_bfloat162(l0,l1);
                *(__nv_bfloat162*)(Chz + (size_t)(r + 8) * ldc + cc) = __nv_bfloat162(h2,h3);
                *(__nv_bfloat162*)(Clz + (size_t)(r + 8) * ldc + cc) = __nv_bfloat162(l2,l3);
            }
        }
    }
}

// ---------------- host launcher ----------------
extern "C" void kernel_launch(void* const* d_in, const int* in_sizes, int n_in,
                              void* d_out, int out_size)
{
    const float* hs    = (const float*)d_in[0];
    const float* resid = (const float*)d_in[1];
    const float* cosp  = (const float*)d_in[2];
    const float* sinp  = (const float*)d_in[3];
    const float* w_qkv = (const float*)d_in[4];
    const float* w_o   = (const float*)d_in[5];
    const float* w_gu  = (const float*)d_in[6];
    const float* w_dn  = (const float*)d_in[7];
    const float* ln1   = (const float*)d_in[8];
    const float* ln2   = (const float*)d_in[9];

    float* out     = (float*)d_out;
    float* mlp_out = out;
    float* res2    = out + (size_t)Tc * Hc;

    float *p_res1, *p_qkv, *p_scores, *p_gu;
    cudaGetSymbolAddress((void**)&p_res1,   g_res1);
    cudaGetSymbolAddress((void**)&p_qkv,    g_qkv);
    cudaGetSymbolAddress((void**)&p_scores, g_scores);
    cudaGetSymbolAddress((void**)&p_gu,     g_gu);
    __nv_bfloat16 *nh,*nl,*qh,*ql,*kh,*kl,*vth,*vtl,*ph,*pl,*ath,*atl,*ach,*acl;
    __nv_bfloat16 *wqh,*wql,*woh,*wol,*wgh,*wgl,*wdh,*wdl;
    cudaGetSymbolAddress((void**)&nh,  g_n_hi);  cudaGetSymbolAddress((void**)&nl,  g_n_lo);
    cudaGetSymbolAddress((void**)&qh,  g_q_hi);  cudaGetSymbolAddress((void**)&ql,  g_q_lo);
    cudaGetSymbolAddress((void**)&kh,  g_k_hi);  cudaGetSymbolAddress((void**)&kl,  g_k_lo);
    cudaGetSymbolAddress((void**)&vth, g_vt_hi); cudaGetSymbolAddress((void**)&vtl, g_vt_lo);
    cudaGetSymbolAddress((void**)&ph,  g_p_hi);  cudaGetSymbolAddress((void**)&pl,  g_p_lo);
    cudaGetSymbolAddress((void**)&ath, g_at_hi); cudaGetSymbolAddress((void**)&atl, g_at_lo);
    cudaGetSymbolAddress((void**)&ach, g_ac_hi); cudaGetSymbolAddress((void**)&acl, g_ac_lo);
    cudaGetSymbolAddress((void**)&wqh, g_wqkv_hi); cudaGetSymbolAddress((void**)&wql, g_wqkv_lo);
    cudaGetSymbolAddress((void**)&woh, g_wo_hi);   cudaGetSymbolAddress((void**)&wol, g_wo_lo);
    cudaGetSymbolAddress((void**)&wgh, g_wgu_hi);  cudaGetSymbolAddress((void**)&wgl, g_wgu_lo);
    cudaGetSymbolAddress((void**)&wdh, g_wdn_hi);  cudaGetSymbolAddress((void**)&wdl, g_wdn_lo);

    cudaFuncSetAttribute(hmma_gemm_kernel<false,false,false,false>, cudaFuncAttributeMaxDynamicSharedMemorySize, gk::SMEM_SZ);
    cudaFuncSetAttribute(hmma_gemm_kernel<true, false,false,false>, cudaFuncAttributeMaxDynamicSharedMemorySize, gk::SMEM_SZ);
    cudaFuncSetAttribute(hmma_gemm_kernel<false,true, false,true >, cudaFuncAttributeMaxDynamicSharedMemorySize, gk::SMEM_SZ);
    cudaFuncSetAttribute(hmma_gemm_kernel<false,false,true, false>, cudaFuncAttributeMaxDynamicSharedMemorySize, gk::SMEM_SZ);

    // weight transposes + hi/lo conversion
    transpose_convert_kernel<<<dim3(3*Hc/32, Hc/32, 1), 256>>>(w_qkv, 0, 0, 3*Hc, wqh, wql, 0, Hc);
    transpose_convert_kernel<<<dim3(Hc/32,   Hc/32, 1), 256>>>(w_o,   0, 0, Hc,   woh, wol, 0, Hc);
    transpose_convert_kernel<<<dim3(2*Ic/32, Hc/32, 1), 256>>>(w_gu,  0, 0, 2*Ic, wgh, wgl, 0, Hc);
    transpose_convert_kernel<<<dim3(Hc/32,   Ic/32, 1), 256>>>(w_dn,  0, 0, Hc,   wdh, wdl, 0, Ic);

    // 1) res1 + RMSNorm -> n planes
    add_rmsnorm_kernel<<<Tc, 256>>>(hs, resid, ln1, p_res1, nh, nl);

    // 2) qkv = normed @ w_qkv (fp32)
    hmma_gemm_kernel<false,false,false,false><<<dim3(3*Hc/128, Tc/256, 1), 256, gk::SMEM_SZ>>>(
        nh, nl, wqh, wql, p_qkv, nullptr, nullptr, nullptr,
        Hc, Hc, Hc, 3*Hc, 0,0,0,0,0,0, 1.f);

    // 3) RoPE -> q/k planes
    rope_kernel<<<(Tc*2*NHc*HALFc)/256, 256>>>(p_qkv, cosp, sinp, qh, ql, kh, kl);

    // 3b) V transpose -> vt planes [z][HD][S]
    transpose_convert_kernel<<<dim3(HDc/32, Sc/32, Bc*NHc), 256>>>(
        p_qkv + 2*Hc, (long long)Sc*3*Hc, HDc, 3*Hc, vth, vtl, (long long)HDc*Sc, Sc);

    // 4) scores = scale * Q @ K^T (causal skip)
    hmma_gemm_kernel<true,false,false,false><<<dim3(Sc/128, Sc/256, Bc*NHc), 256, gk::SMEM_SZ>>>(
        qh, ql, kh, kl, p_scores, nullptr, nullptr, nullptr,
        HDc, Hc, Hc, Sc,
        (long long)Sc*Hc, HDc, (long long)Sc*Hc, HDc,
        (long long)NHc*Sc*Sc, (long long)Sc*Sc, SCALEc);

    // 5) softmax -> P planes
    softmax_kernel<<<dim3(Sc, Bc*NHc), 256>>>(p_scores, ph, pl);

    // 6) attn = P @ V (K-limited to rowBase+256) -> at planes (hi/lo)
    hmma_gemm_kernel<false,true,false,true><<<dim3(1, Sc/256, Bc*NHc), 256, gk::SMEM_SZ>>>(
        ph, pl, vth, vtl, nullptr, ath, atl, nullptr,
        Sc, Sc, Sc, Hc,
        (long long)NHc*Sc*Sc, (long long)Sc*Sc,
        (long long)NHc*HDc*Sc, (long long)HDc*Sc,
        (long long)Sc*Hc, HDc, 1.f);

    // 7) res2 = attn @ w_o + res1 (fp32, into output)
    hmma_gemm_kernel<false,false,true,false><<<dim3(Hc/128, Tc/256, 1), 256, gk::SMEM_SZ>>>(
        ath, atl, woh, wol, res2, nullptr, nullptr, p_res1,
        Hc, Hc, Hc, Hc, 0,0,0,0,0,0, 1.f);

    // 8) RMSNorm(res2) -> n planes
    add_rmsnorm_kernel<<<Tc, 256>>>(res2, nullptr, ln2, nullptr, nh, nl);

    // 9) gu = normed2 @ w_gate_up (fp32)
    hmma_gemm_kernel<false,false,false,false><<<dim3(2*Ic/128, Tc/256, 1), 256, gk::SMEM_SZ>>>(
        nh, nl, wgh, wgl, p_gu, nullptr, nullptr, nullptr,
        Hc, Hc, Hc, 2*Ic, 0,0,0,0,0,0, 1.f);

    // 10) silu*up -> ac planes
    silu_mul_kernel<<<dim3(Ic/256, Tc), 256>>>(p_gu, ach, acl);

    // 11) mlp_out = act @ w_down (fp32, into output)
    hmma_gemm_kernel<false,false,false,false><<<dim3(Hc/128, Tc/256, 1), 256, gk::SMEM_SZ>>>(
        ach, acl, wdh, wdl, mlp_out, nullptr, nullptr, nullptr,
        Ic, Ic, Ic, Hc, 0,0,0,0,0,0, 1.f);
}

// round 7
// speedup vs baseline: 2.3377x; 1.0002x over previous
#include <cuda_runtime.h>
#include <cuda_bf16.h>
#include <math.h>
#include <stdint.h>

namespace {
constexpr int Bc  = 2;
constexpr int Sc  = 2048;
constexpr int Hc  = 4096;
constexpr int NHc = 32;
constexpr int HDc = 128;
constexpr int Ic  = 11008;
constexpr int Tc  = Bc * Sc;
constexpr int HALFc = HDc / 2;
constexpr float EPSc = 1e-6f;
constexpr float SCALEc = 0.08838834764831843f;
}

// ---------------- device scratch ----------------
__device__ float g_res1  [(size_t)Tc * Hc];
__device__ float g_qkv   [(size_t)Tc * 3 * Hc];
__device__ float g_scores[(size_t)Bc * NHc * Sc * Sc];
__device__ float g_gu    [(size_t)Tc * 2 * Ic];

__device__ __nv_bfloat16 g_n_hi [(size_t)Tc * Hc],  g_n_lo [(size_t)Tc * Hc];
__device__ __nv_bfloat16 g_q_hi [(size_t)Tc * Hc],  g_q_lo [(size_t)Tc * Hc];
__device__ __nv_bfloat16 g_k_hi [(size_t)Tc * Hc],  g_k_lo [(size_t)Tc * Hc];
__device__ __nv_bfloat16 g_vt_hi[(size_t)Tc * Hc],  g_vt_lo[(size_t)Tc * Hc];
__device__ __nv_bfloat16 g_p_hi [(size_t)Bc * NHc * Sc * Sc];
__device__ __nv_bfloat16 g_p_lo [(size_t)Bc * NHc * Sc * Sc];
__device__ __nv_bfloat16 g_at_hi[(size_t)Tc * Hc],  g_at_lo[(size_t)Tc * Hc];
__device__ __nv_bfloat16 g_ac_hi[(size_t)Tc * Ic],  g_ac_lo[(size_t)Tc * Ic];
__device__ __nv_bfloat16 g_wqkv_hi[(size_t)Hc * 3 * Hc], g_wqkv_lo[(size_t)Hc * 3 * Hc];
__device__ __nv_bfloat16 g_wo_hi  [(size_t)Hc * Hc],     g_wo_lo  [(size_t)Hc * Hc];
__device__ __nv_bfloat16 g_wgu_hi [(size_t)Hc * 2 * Ic], g_wgu_lo [(size_t)Hc * 2 * Ic];
__device__ __nv_bfloat16 g_wdn_hi [(size_t)Ic * Hc],     g_wdn_lo [(size_t)Ic * Hc];

// ---------------- helpers ----------------
__device__ __forceinline__ uint32_t smem_u32(const void* p) {
    return (uint32_t)__cvta_generic_to_shared(p);
}
__device__ __forceinline__ void ldsm_x4(uint32_t (&r)[4], uint32_t addr) {
    asm volatile("ldmatrix.sync.aligned.m8n8.x4.shared.b16 {%0,%1,%2,%3}, [%4];"
                 : "=r"(r[0]), "=r"(r[1]), "=r"(r[2]), "=r"(r[3]) : "r"(addr));
}
__device__ __forceinline__ void mma_bf16(float (&d)[4], const uint32_t (&a)[4],
                                         uint32_t b0, uint32_t b1) {
    asm volatile("mma.sync.aligned.m16n8k16.row.col.f32.bf16.bf16.f32 "
        "{%0,%1,%2,%3}, {%4,%5,%6,%7}, {%8,%9}, {%0,%1,%2,%3};"
        : "+f"(d[0]), "+f"(d[1]), "+f"(d[2]), "+f"(d[3])
        : "r"(a[0]), "r"(a[1]), "r"(a[2]), "r"(a[3]), "r"(b0), "r"(b1));
}
__device__ __forceinline__ void cp_async16(uint32_t dst, const void* src) {
    asm volatile("cp.async.cg.shared.global [%0], [%1], 16;" :: "r"(dst), "l"(src));
}
#define CP_COMMIT() asm volatile("cp.async.commit_group;" ::: "memory")
#define CP_WAIT(n)  asm volatile("cp.async.wait_group %0;" :: "n"(n) : "memory")
__device__ __forceinline__ void split2(float v, __nv_bfloat16& h, __nv_bfloat16& l) {
    h = __float2bfloat16(v);
    l = __float2bfloat16(v - __bfloat162float(h));
}

// ---------------- block reductions ----------------
__device__ __forceinline__ float block_reduce_sum_256(float v) {
    #pragma unroll
    for (int o = 16; o > 0; o >>= 1) v += __shfl_down_sync(0xffffffffu, v, o);
    __shared__ float red[8];
    int w = threadIdx.x >> 5, l = threadIdx.x & 31;
    if (l == 0) red[w] = v;
    __syncthreads();
    if (w == 0) {
        float x = (l < 8) ? red[l] : 0.f;
        #pragma unroll
        for (int o = 4; o > 0; o >>= 1) x += __shfl_down_sync(0xffu, x, o);
        if (l == 0) red[0] = x;
    }
    __syncthreads();
    float r = red[0];
    __syncthreads();
    return r;
}
__device__ __forceinline__ float block_reduce_max_256(float v) {
    #pragma unroll
    for (int o = 16; o > 0; o >>= 1) v = fmaxf(v, __shfl_down_sync(0xffffffffu, v, o));
    __shared__ float red[8];
    int w = threadIdx.x >> 5, l = threadIdx.x & 31;
    if (l == 0) red[w] = v;
    __syncthreads();
    if (w == 0) {
        float x = (l < 8) ? red[l] : -INFINITY;
        #pragma unroll
        for (int o = 4; o > 0; o >>= 1) x = fmaxf(x, __shfl_down_sync(0xffu, x, o));
        if (l == 0) red[0] = x;
    }
    __syncthreads();
    float r = red[0];
    __syncthreads();
    return r;
}

// ---------------- add + RMSNorm -> hi/lo ----------------
__global__ __launch_bounds__(256) void add_rmsnorm_kernel(
    const float* __restrict__ a, const float* __restrict__ b,
    const float* __restrict__ w, float* __restrict__ sum_out,
    __nv_bfloat16* __restrict__ ohi, __nv_bfloat16* __restrict__ olo)
{
    int row = blockIdx.x;
    const float4* a4 = (const float4*)(a + (size_t)row * Hc);
    const float4* b4 = b ? (const float4*)(b + (size_t)row * Hc) : nullptr;
    const float4* w4 = (const float4*)w;
    float4* s4 = sum_out ? (float4*)(sum_out + (size_t)row * Hc) : nullptr;
    __nv_bfloat162* oh2 = (__nv_bfloat162*)(ohi + (size_t)row * Hc);
    __nv_bfloat162* ol2 = (__nv_bfloat162*)(olo + (size_t)row * Hc);

    float4 v[4];
    float ss = 0.f;
    #pragma unroll
    for (int it = 0; it < 4; it++) {
        int idx = threadIdx.x + it * 256;
        float4 va = a4[idx];
        if (b4) { float4 vb = b4[idx]; va.x += vb.x; va.y += vb.y; va.z += vb.z; va.w += vb.w; }
        v[it] = va;
        ss += va.x * va.x + va.y * va.y + va.z * va.z + va.w * va.w;
    }
    float tot = block_reduce_sum_256(ss);
    float scale = rsqrtf(tot / (float)Hc + EPSc);
    #pragma unroll
    for (int it = 0; it < 4; it++) {
        int idx = threadIdx.x + it * 256;
        if (s4) s4[idx] = v[it];
        float4 vw = w4[idx];
        float y0 = v[it].x * scale * vw.x, y1 = v[it].y * scale * vw.y;
        float y2 = v[it].z * scale * vw.z, y3 = v[it].w * scale * vw.w;
        __nv_bfloat16 h0,l0,h1,l1,h2,l2,h3,l3;
        split2(y0,h0,l0); split2(y1,h1,l1); split2(y2,h2,l2); split2(y3,h3,l3);
        oh2[idx*2]   = __nv_bfloat162(h0,h1);
        oh2[idx*2+1] = __nv_bfloat162(h2,h3);
        ol2[idx*2]   = __nv_bfloat162(l0,l1);
        ol2[idx*2+1] = __nv_bfloat162(l2,l3);
    }
}

// ---------------- RoPE: fp32 qkv -> Q/K hi/lo ----------------
__global__ __launch_bounds__(256) void rope_kernel(
    const float* __restrict__ qkv, const float* __restrict__ cosp,
    const float* __restrict__ sinp,
    __nv_bfloat16* __restrict__ qhi, __nv_bfloat16* __restrict__ qlo,
    __nv_bfloat16* __restrict__ khi, __nv_bfloat16* __restrict__ klo)
{
    int idx = blockIdx.x * 256 + threadIdx.x;
    int d = idx & (HALFc - 1);
    int h = (idx >> 6) & (NHc - 1);
    int m = (idx >> 11) & 1;
    int t = idx >> 12;
    const float* p = qkv + (size_t)t * (3 * Hc) + m * Hc + h * HDc + d;
    float x1 = p[0], x2 = p[HALFc];
    float c = cosp[(size_t)t * HALFc + d];
    float s = sinp[(size_t)t * HALFc + d];
    float y1 = x1 * c - x2 * s;
    float y2 = x1 * s + x2 * c;
    __nv_bfloat16* dh = (m ? khi : qhi) + (size_t)t * Hc + h * HDc + d;
    __nv_bfloat16* dl = (m ? klo : qlo) + (size_t)t * Hc + h * HDc + d;
    __nv_bfloat16 h1, l1, h2, l2;
    split2(y1, h1, l1); split2(y2, h2, l2);
    dh[0] = h1; dh[HALFc] = h2;
    dl[0] = l1; dl[HALFc] = l2;
}

// ------- transpose fp32 [Y,X] (ld=in_ld) -> hi/lo [X,Y]; batched via z -------
__global__ __launch_bounds__(256) void transpose_convert_kernel(
    const float* __restrict__ in, long long inSb, long long inSh, int in_ld,
    __nv_bfloat16* __restrict__ ohi, __nv_bfloat16* __restrict__ olo,
    long long outSz, int Y)
{
    __shared__ float tile[32][33];
    int z = blockIdx.z, zb = z / NHc, zh = z % NHc;
    const float* inp = in + zb * inSb + zh * inSh;
    __nv_bfloat16* oh = ohi + (long long)z * outSz;
    __nv_bfloat16* ol = olo + (long long)z * outSz;
    int tx = threadIdx.x & 31, ty = threadIdx.x >> 5;
    int gx = blockIdx.x * 32 + tx;
    #pragma unroll
    for (int i = 0; i < 4; i++) {
        int gy = blockIdx.y * 32 + ty + i * 8;
        tile[ty + i * 8][tx] = inp[(size_t)gy * in_ld + gx];
    }
    __syncthreads();
    int ox = blockIdx.y * 32 + tx;
    #pragma unroll
    for (int i = 0; i < 4; i++) {
        int oy = blockIdx.x * 32 + ty + i * 8;
        float v = tile[tx][ty + i * 8];
        __nv_bfloat16 h, l;
        split2(v, h, l);
        oh[(size_t)oy * Y + ox] = h;
        ol[(size_t)oy * Y + ox] = l;
    }
}

// ------- causal softmax -> P hi/lo (zero-fill to 256-aligned edge) -------
__global__ __launch_bounds__(256) void softmax_kernel(
    const float* __restrict__ scores,
    __nv_bfloat16* __restrict__ phi, __nv_bfloat16* __restrict__ plo)
{
    int i = blockIdx.x;
    int z = blockIdx.y;
    const float* row = scores + (size_t)z * Sc * Sc + (size_t)i * Sc;
    __nv_bfloat16* ph = phi + (size_t)z * Sc * Sc + (size_t)i * Sc;
    __nv_bfloat16* pl = plo + (size_t)z * Sc * Sc + (size_t)i * Sc;
    int nvalid = i + 1;

    float vals[8];
    float mx = -INFINITY;
    #pragma unroll
    for (int it = 0; it < 8; it++) {
        int j = threadIdx.x + it * 256;
        float v = (j < nvalid) ? row[j] : -INFINITY;
        vals[it] = v;
        mx = fmaxf(mx, v);
    }
    float M = block_reduce_max_256(mx);
    float sum = 0.f;
    #pragma unroll
    for (int it = 0; it < 8; it++) {
        int j = threadIdx.x + it * 256;
        float e = (j < nvalid) ? __expf(vals[it] - M) : 0.f;
        vals[it] = e;
        sum += e;
    }
    float tot = block_reduce_sum_256(sum);
    float inv = 1.f / tot;
    int zero_end = ((i >> 8) + 1) << 8;   // 256-aligned (matches PV BM=256 K-limit)
    #pragma unroll
    for (int it = 0; it < 8; it++) {
        int j = threadIdx.x + it * 256;
        if (j < zero_end) {
            float p = vals[it] * inv;
            __nv_bfloat16 h, l;
            split2(p, h, l);
            ph[j] = h; pl[j] = l;
        }
    }
}

// ---------------- SiLU(gate)*up -> hi/lo ----------------
__global__ __launch_bounds__(256) void silu_mul_kernel(
    const float* __restrict__ gu,
    __nv_bfloat16* __restrict__ ahi, __nv_bfloat16* __restrict__ alo)
{
    int t = blockIdx.y;
    int i = blockIdx.x * 256 + threadIdx.x;
    float g = gu[(size_t)t * (2 * Ic) + i];
    float u = gu[(size_t)t * (2 * Ic) + Ic + i];
    float s = g / (1.f + __expf(-g));
    float y = s * u;
    __nv_bfloat16 h, l;
    split2(y, h, l);
    ahi[(size_t)t * Ic + i] = h;
    alo[(size_t)t * Ic + i] = l;
}

// ------------------------------------------------------------------
// HMMA GEMM: C = alpha*(A@B^T)[+ADD]. A:[M,K], B:[N,K] hi/lo K-major
// bf16 planes. BM=256, BN=128, BK=32. 8 warps, 64x64 warp tiles
// (mt=nt=4, balanced ldsm/mma). cp.async 2-stage pipeline.
// 3 passes (hh, hl, lh) into shared fp32 accumulators.
// ------------------------------------------------------------------
namespace gk {
constexpr int BM = 256, BN = 128, BK = 32, SROW = 40;
constexpr int AOFF_L = BM * SROW * 2;           // 20480
constexpr int BOFF_H = 2 * AOFF_L;              // 40960
constexpr int BOFF_L = BOFF_H + BN * SROW * 2;  // 51200
constexpr int STAGE  = BOFF_L + BN * SROW * 2;  // 61440
constexpr int SMEM_SZ = 2 * STAGE;              // 122880
}

template<bool CAUSAL, bool KLIM, bool ADDC, bool HILO>
__global__ __launch_bounds__(256, 1) void hmma_gemm_kernel(
    const __nv_bfloat16* __restrict__ Ahi, const __nv_bfloat16* __restrict__ Alo,
    const __nv_bfloat16* __restrict__ Bhi, const __nv_bfloat16* __restrict__ Blo,
    float* __restrict__ Cf, __nv_bfloat16* __restrict__ Chi, __nv_bfloat16* __restrict__ Clo,
    const float* __restrict__ ADDp,
    int K, int lda, int ldb, int ldc,
    long long sAb, long long sAh_, long long sBb, long long sBh_,
    long long sCb, long long sCh_, float alpha)
{
    using namespace gk;
    int rowBase = blockIdx.y * BM;
    int colBase = blockIdx.x * BN;
    if (CAUSAL && colBase > rowBase + BM - 1) return;

    extern __shared__ __nv_bfloat16 smem[];
    uint32_t sbase = smem_u32(smem);

    int tid = threadIdx.x;
    int wid = tid >> 5, lane = tid & 31;
    int wm = wid & 3, wn = wid >> 2;          // 4 x 2 warp grid, 64x64 tiles

    int z = blockIdx.z, zb = z / NHc, zh = z % NHc;
    const __nv_bfloat16* Ah = Ahi + zb * sAb + zh * sAh_;
    const __nv_bfloat16* Al = Alo + zb * sAb + zh * sAh_;
    const __nv_bfloat16* Bh = Bhi + zb * sBb + zh * sBh_;
    const __nv_bfloat16* Bl = Blo + zb * sBb + zh * sBh_;

    int kEnd = KLIM ? min(K, rowBase + BM) : K;
    int nch  = kEnd / BK;

    float acc[4][8][4];
    #pragma unroll
    for (int a = 0; a < 4; a++)
        #pragma unroll
        for (int b = 0; b < 8; b++)
            #pragma unroll
            for (int c = 0; c < 4; c++) acc[a][b][c] = 0.f;

    // cp.async mapping: i -> row=i>>2, 16B seg=(i&3)*8 elems
    int ar = tid >> 2, sg = (tid & 3) * 8;
    uint32_t soff = (uint32_t)(ar * SROW + sg) * 2;

    auto issue = [&](int c, int s) {
        int k0 = c * BK;
        uint32_t st = sbase + s * STAGE;
        #pragma unroll
        for (int it = 0; it < 4; it++) {
            int r = ar + it * 64;
            uint32_t o = soff + (uint32_t)(it * 64 * SROW) * 2;
            cp_async16(st + o,          Ah + (size_t)(rowBase + r) * lda + k0 + sg);
            cp_async16(st + AOFF_L + o, Al + (size_t)(rowBase + r) * lda + k0 + sg);
        }
        #pragma unroll
        for (int it = 0; it < 2; it++) {
            int r = ar + it * 64;
            uint32_t o = soff + (uint32_t)(it * 64 * SROW) * 2;
            cp_async16(st + BOFF_H + o, Bh + (size_t)(colBase + r) * ldb + k0 + sg);
            cp_async16(st + BOFF_L + o, Bl + (size_t)(colBase + r) * ldb + k0 + sg);
        }
    };

    // ldmatrix lane addressing
    int mat = lane >> 3, r8 = lane & 7;
    int a_row = (mat & 1) * 8 + r8, a_k = (mat >> 1) * 8;
    int b_n   = (mat >> 1) * 8 + r8, b_k = (mat & 1) * 8;

    issue(0, 0); CP_COMMIT();

    for (int c = 0; c < nch; ++c) {
        if (c + 1 < nch) { issue(c + 1, (c + 1) & 1); CP_COMMIT(); CP_WAIT(1); }
        else             { CP_WAIT(0); }
        __syncthreads();

        uint32_t st = sbase + (c & 1) * STAGE;
        #pragma unroll
        for (int ks = 0; ks < 2; ++ks) {
            uint32_t ah[4][4], al[4][4];
            #pragma unroll
            for (int mt = 0; mt < 4; ++mt) {
                uint32_t off = (uint32_t)((wm * 64 + mt * 16 + a_row) * SROW
                                          + ks * 16 + a_k) * 2;
                ldsm_x4(ah[mt], st + off);
                ldsm_x4(al[mt], st + AOFF_L + off);
            }
            #pragma unroll
            for (int nt = 0; nt < 4; ++nt) {
                uint32_t boff = (uint32_t)((wn * 64 + nt * 16 + b_n) * SROW
                                           + ks * 16 + b_k) * 2;
                uint32_t bh[4], bl[4];
                ldsm_x4(bh, st + BOFF_H + boff);
                ldsm_x4(bl, st + BOFF_L + boff);
                #pragma unroll
                for (int mt = 0; mt < 4; ++mt) {
                    #pragma unroll
                    for (int h2 = 0; h2 < 2; ++h2) {
                        mma_bf16(acc[mt][nt*2+h2], ah[mt], bh[2*h2], bh[2*h2+1]);
                        mma_bf16(acc[mt][nt*2+h2], ah[mt], bl[2*h2], bl[2*h2+1]);
                        mma_bf16(acc[mt][nt*2+h2], al[mt], bh[2*h2], bh[2*h2+1]);
                    }
                }
            }
        }
        __syncthreads();
    }

    // ---------------- epilogue ----------------
    float*         Cfz = Cf  ? Cf  + zb * sCb + zh * sCh_ : nullptr;
    __nv_bfloat16* Chz = Chi ? Chi + zb * sCb + zh * sCh_ : nullptr;
    __nv_bfloat16* Clz = Clo ? Clo + zb * sCb + zh * sCh_ : nullptr;
    const float*   ADz = ADDp ? ADDp + zb * sCb + zh * sCh_ : nullptr;

    #pragma unroll
    for (int mt = 0; mt < 4; ++mt) {
        int r = rowBase + wm * 64 + mt * 16 + (lane >> 2);
        #pragma unroll
        for (int j8 = 0; j8 < 8; ++j8) {
            int cc = colBase + wn * 64 + j8 * 8 + 2 * (lane & 3);
            float v0 = acc[mt][j8][0] * alpha;
            float v1 = acc[mt][j8][1] * alpha;
            float v2 = acc[mt][j8][2] * alpha;
            float v3 = acc[mt][j8][3] * alpha;
            if (ADDC) {
                float2 a0 = *(const float2*)(ADz + (size_t)r * ldc + cc);
                float2 a1 = *(const float2*)(ADz + (size_t)(r + 8) * ldc + cc);
                v0 += a0.x; v1 += a0.y; v2 += a1.x; v3 += a1.y;
            }
            if (!HILO) {
                *(float2*)(Cfz + (size_t)r * ldc + cc)       = make_float2(v0, v1);
                *(float2*)(Cfz + (size_t)(r + 8) * ldc + cc) = make_float2(v2, v3);
            } else {
                __nv_bfloat16 h0,l0,h1,l1,h2,l2,h3,l3;
                split2(v0,h0,l0); split2(v1,h1,l1);
                split2(v2,h2,l2); split2(v3,h3,l3);
                *(__nv_bfloat162*)(Chz + (size_t)r * ldc + cc)       = __nv_bfloat162(h0,h1);
                *(__nv_bfloat162*)(Clz + (size_t)r * ldc + cc)       = __nv_bfloat162(l0,l1);
                *(__nv_bfloat162*)(Chz + (size_t)(r + 8) * ldc + cc) = __nv_bfloat162(h2,h3);
                *(__nv_bfloat162*)(Clz + (size_t)(r + 8) * ldc + cc) = __nv_bfloat162(l2,l3);
            }
        }
    }
}

// ---------------- host launcher ----------------
extern "C" void kernel_launch(void* const* d_in, const int* in_sizes, int n_in,
                              void* d_out, int out_size)
{
    const float* hs    = (const float*)d_in[0];
    const float* resid = (const float*)d_in[1];
    const float* cosp  = (const float*)d_in[2];
    const float* sinp  = (const float*)d_in[3];
    const float* w_qkv = (const float*)d_in[4];
    const float* w_o   = (const float*)d_in[5];
    const float* w_gu  = (const float*)d_in[6];
    const float* w_dn  = (const float*)d_in[7];
    const float* ln1   = (const float*)d_in[8];
    const float* ln2   = (const float*)d_in[9];

    float* out     = (float*)d_out;
    float* mlp_out = out;
    float* res2    = out + (size_t)Tc * Hc;

    float *p_res1, *p_qkv, *p_scores, *p_gu;
    cudaGetSymbolAddress((void**)&p_res1,   g_res1);
    cudaGetSymbolAddress((void**)&p_qkv,    g_qkv);
    cudaGetSymbolAddress((void**)&p_scores, g_scores);
    cudaGetSymbolAddress((void**)&p_gu,     g_gu);
    __nv_bfloat16 *nh,*nl,*qh,*ql,*kh,*kl,*vth,*vtl,*ph,*pl,*ath,*atl,*ach,*acl;
    __nv_bfloat16 *wqh,*wql,*woh,*wol,*wgh,*wgl,*wdh,*wdl;
    cudaGetSymbolAddress((void**)&nh,  g_n_hi);  cudaGetSymbolAddress((void**)&nl,  g_n_lo);
    cudaGetSymbolAddress((void**)&qh,  g_q_hi);  cudaGetSymbolAddress((void**)&ql,  g_q_lo);
    cudaGetSymbolAddress((void**)&kh,  g_k_hi);  cudaGetSymbolAddress((void**)&kl,  g_k_lo);
    cudaGetSymbolAddress((void**)&vth, g_vt_hi); cudaGetSymbolAddress((void**)&vtl, g_vt_lo);
    cudaGetSymbolAddress((void**)&ph,  g_p_hi);  cudaGetSymbolAddress((void**)&pl,  g_p_lo);
    cudaGetSymbolAddress((void**)&ath, g_at_hi); cudaGetSymbolAddress((void**)&atl, g_at_lo);
    cudaGetSymbolAddress((void**)&ach, g_ac_hi); cudaGetSymbolAddress((void**)&acl, g_ac_lo);
    cudaGetSymbolAddress((void**)&wqh, g_wqkv_hi); cudaGetSymbolAddress((void**)&wql, g_wqkv_lo);
    cudaGetSymbolAddress((void**)&woh, g_wo_hi);   cudaGetSymbolAddress((void**)&wol, g_wo_lo);
    cudaGetSymbolAddress((void**)&wgh, g_wgu_hi);  cudaGetSymbolAddress((void**)&wgl, g_wgu_lo);
    cudaGetSymbolAddress((void**)&wdh, g_wdn_hi);  cudaGetSymbolAddress((void**)&wdl, g_wdn_lo);

    cudaFuncSetAttribute(hmma_gemm_kernel<false,false,false,false>, cudaFuncAttributeMaxDynamicSharedMemorySize, gk::SMEM_SZ);
    cudaFuncSetAttribute(hmma_gemm_kernel<true, false,false,false>, cudaFuncAttributeMaxDynamicSharedMemorySize, gk::SMEM_SZ);
    cudaFuncSetAttribute(hmma_gemm_kernel<false,true, false,true >, cudaFuncAttributeMaxDynamicSharedMemorySize, gk::SMEM_SZ);
    cudaFuncSetAttribute(hmma_gemm_kernel<false,false,true, false>, cudaFuncAttributeMaxDynamicSharedMemorySize, gk::SMEM_SZ);

    // weight transposes + hi/lo conversion
    transpose_convert_kernel<<<dim3(3*Hc/32, Hc/32, 1), 256>>>(w_qkv, 0, 0, 3*Hc, wqh, wql, 0, Hc);
    transpose_convert_kernel<<<dim3(Hc/32,   Hc/32, 1), 256>>>(w_o,   0, 0, Hc,   woh, wol, 0, Hc);
    transpose_convert_kernel<<<dim3(2*Ic/32, Hc/32, 1), 256>>>(w_gu,  0, 0, 2*Ic, wgh, wgl, 0, Hc);
    transpose_convert_kernel<<<dim3(Hc/32,   Ic/32, 1), 256>>>(w_dn,  0, 0, Hc,   wdh, wdl, 0, Ic);

    // 1) res1 + RMSNorm -> n planes
    add_rmsnorm_kernel<<<Tc, 256>>>(hs, resid, ln1, p_res1, nh, nl);

    // 2) qkv = normed @ w_qkv (fp32)
    hmma_gemm_kernel<false,false,false,false><<<dim3(3*Hc/128, Tc/256, 1), 256, gk::SMEM_SZ>>>(
        nh, nl, wqh, wql, p_qkv, nullptr, nullptr, nullptr,
        Hc, Hc, Hc, 3*Hc, 0,0,0,0,0,0, 1.f);

    // 3) RoPE -> q/k planes
    rope_kernel<<<(Tc*2*NHc*HALFc)/256, 256>>>(p_qkv, cosp, sinp, qh, ql, kh, kl);

    // 3b) V transpose -> vt planes [z][HD][S]
    transpose_convert_kernel<<<dim3(HDc/32, Sc/32, Bc*NHc), 256>>>(
        p_qkv + 2*Hc, (long long)Sc*3*Hc, HDc, 3*Hc, vth, vtl, (long long)HDc*Sc, Sc);

    // 4) scores = scale * Q @ K^T (causal skip)
    hmma_gemm_kernel<true,false,false,false><<<dim3(Sc/128, Sc/256, Bc*NHc), 256, gk::SMEM_SZ>>>(
        qh, ql, kh, kl, p_scores, nullptr, nullptr, nullptr,
        HDc, Hc, Hc, Sc,
        (long long)Sc*Hc, HDc, (long long)Sc*Hc, HDc,
        (long long)NHc*Sc*Sc, (long long)Sc*Sc, SCALEc);

    // 5) softmax -> P planes
    softmax_kernel<<<dim3(Sc, Bc*NHc), 256>>>(p_scores, ph, pl);

    // 6) attn = P @ V (K-limited to rowBase+256) -> at planes (hi/lo)
    hmma_gemm_kernel<false,true,false,true><<<dim3(1, Sc/256, Bc*NHc), 256, gk::SMEM_SZ>>>(
        ph, pl, vth, vtl, nullptr, ath, atl, nullptr,
        Sc, Sc, Sc, Hc,
        (long long)NHc*Sc*Sc, (long long)Sc*Sc,
        (long long)NHc*HDc*Sc, (long long)HDc*Sc,
        (long long)Sc*Hc, HDc, 1.f);

    // 7) res2 = attn @ w_o + res1 (fp32, into output)
    hmma_gemm_kernel<false,false,true,false><<<dim3(Hc/128, Tc/256, 1), 256, gk::SMEM_SZ>>>(
        ath, atl, woh, wol, res2, nullptr, nullptr, p_res1,
        Hc, Hc, Hc, Hc, 0,0,0,0,0,0, 1.f);

    // 8) RMSNorm(res2) -> n planes
    add_rmsnorm_kernel<<<Tc, 256>>>(res2, nullptr, ln2, nullptr, nh, nl);

    // 9) gu = normed2 @ w_gate_up (fp32)
    hmma_gemm_kernel<false,false,false,false><<<dim3(2*Ic/128, Tc/256, 1), 256, gk::SMEM_SZ>>>(
        nh, nl, wgh, wgl, p_gu, nullptr, nullptr, nullptr,
        Hc, Hc, Hc, 2*Ic, 0,0,0,0,0,0, 1.f);

    // 10) silu*up -> ac planes
    silu_mul_kernel<<<dim3(Ic/256, Tc), 256>>>(p_gu, ach, acl);

    // 11) mlp_out = act @ w_down (fp32, into output)
    hmma_gemm_kernel<false,false,false,false><<<dim3(Hc/128, Tc/256, 1), 256, gk::SMEM_SZ>>>(
        ach, acl, wdh, wdl, mlp_out, nullptr, nullptr, nullptr,
        Ic, Ic, Ic, Hc, 0,0,0,0,0,0, 1.f);
}